// round 15
// baseline (speedup 1.0000x reference)
#include <cuda_runtime.h>
#include <cuda_bf16.h>
#include <cuda_fp16.h>
#include <math.h>
#include <stdint.h>

// ---------------- problem constants ----------------
#define BB   16
#define NCH  64
#define TT   15000
#define WS   500
#define STp  250
#define NW   59              // (T-WS)/ST + 1
#define NBLK 60              // half-blocks per channel
#define NBINS 58             // k = 2..59
#define DM   512
#define EPSc 1e-6f
#define LN_EPS 1e-5f

#define NROWS_A   (BB*NCH*NBLK)      // 61440  half-block rows
#define NTOK      (BB*NW*NCH)        // 60416
#define NBW       (BB*NW)            // 944
#define HCOLS     128                // padded H width
#define KPAD      256                // padded DFT K (250 -> 256)
#define TOK_ELEMS (NTOK*DM)

#ifndef M_PI
#define M_PI 3.14159265358979323846
#endif

// ---------------- scratch (static device globals) ----------------
__device__ float g_zbias[DM];
__device__ float g_H[(size_t)NROWS_A*HCOLS];
__device__ float g_E[NROWS_A];
__device__ float g_feat[(size_t)NTOK*15];
__device__ float g_bp[(size_t)NTOK*4];
__device__ float g_desc[(size_t)NBW*11];
__device__ float g_hd[(size_t)NBW*DM];
__device__ float g_maskf[BB*NCH];
// bf16 split operands (DFT, 3-pass)
__device__ __nv_bfloat16 g_xh[(size_t)NROWS_A*KPAD];   // x half-blocks hi
__device__ __nv_bfloat16 g_xl[(size_t)NROWS_A*KPAD];   // x half-blocks lo
__device__ __nv_bfloat16 g_bh[HCOLS*KPAD];             // DFT basis^T hi [t][k]
__device__ __nv_bfloat16 g_bl[HCOLS*KPAD];             // DFT basis^T lo
// fp16 operands (token GEMM2, single pass)
__device__ __half g_hh[(size_t)NTOK*DM];               // fp16(gelu(feat W1 + b1))
__device__ __half g_wh[DM*DM];                         // Wf2^T fp16 [n][k]

// ================= portable PTX helpers (sm_80+ baseline) ==================
__device__ __forceinline__ uint32_t smem_u32(const void* p) {
    uint32_t a;
    asm("{ .reg .u64 t; cvta.to.shared.u64 t, %1; cvt.u32.u64 %0, t; }"
        : "=r"(a) : "l"(p));
    return a;
}

// Swizzle for 64-byte-wide rows (Swizzle<2,4,3>)
#define SWZ64(off)  ((off) ^ (((off) >> 3) & 0x30))

#define CP_ASYNC16(dst, src) \
    asm volatile("cp.async.cg.shared.global [%0], [%1], 16;" :: "r"(dst), "l"(src))
#define CP_COMMIT() asm volatile("cp.async.commit_group;" ::: "memory")
#define CP_WAIT0()  asm volatile("cp.async.wait_group 0;" ::: "memory")
#define CP_WAIT1()  asm volatile("cp.async.wait_group 1;" ::: "memory")

__device__ __forceinline__ void ldsm_x4(uint32_t& r0, uint32_t& r1,
                                        uint32_t& r2, uint32_t& r3, uint32_t addr) {
    asm volatile("ldmatrix.sync.aligned.m8n8.x4.shared.b16 {%0,%1,%2,%3}, [%4];"
                 : "=r"(r0), "=r"(r1), "=r"(r2), "=r"(r3) : "r"(addr));
}
__device__ __forceinline__ void ldsm_x2(uint32_t& r0, uint32_t& r1, uint32_t addr) {
    asm volatile("ldmatrix.sync.aligned.m8n8.x2.shared.b16 {%0,%1}, [%2];"
                 : "=r"(r0), "=r"(r1) : "r"(addr));
}
__device__ __forceinline__ void mma_bf16(float* c, const uint32_t* a, const uint32_t* b) {
    asm volatile(
        "mma.sync.aligned.m16n8k16.row.col.f32.bf16.bf16.f32 "
        "{%0,%1,%2,%3}, {%4,%5,%6,%7}, {%8,%9}, {%0,%1,%2,%3};"
        : "+f"(c[0]), "+f"(c[1]), "+f"(c[2]), "+f"(c[3])
        : "r"(a[0]), "r"(a[1]), "r"(a[2]), "r"(a[3]), "r"(b[0]), "r"(b[1]));
}
__device__ __forceinline__ void mma_f16(float* c, const uint32_t* a, const uint32_t* b) {
    asm volatile(
        "mma.sync.aligned.m16n8k16.row.col.f32.f16.f16.f32 "
        "{%0,%1,%2,%3}, {%4,%5,%6,%7}, {%8,%9}, {%0,%1,%2,%3};"
        : "+f"(c[0]), "+f"(c[1]), "+f"(c[2]), "+f"(c[3])
        : "r"(a[0]), "r"(a[1]), "r"(a[2]), "r"(a[3]), "r"(b[0]), "r"(b[1]));
}

// ---------------- mask dtype detection + conversion ----------------
__global__ void mask_convert_kernel(const void* mptr) {
    __shared__ int s_anyFloat, s_anyHighByte, s_mode;
    int tid = threadIdx.x;
    if (tid == 0) { s_anyFloat = 0; s_anyHighByte = 0; }
    __syncthreads();
    unsigned int w = ((const unsigned int*)mptr)[tid];
    if (w == 0x3F800000u) atomicOr(&s_anyFloat, 1);
    else if ((w & 0xFFFFFF00u) != 0u) atomicOr(&s_anyHighByte, 1);
    __syncthreads();
    if (tid == 0)
        s_mode = s_anyFloat ? 2 : (s_anyHighByte ? 0 : 1);
    __syncthreads();
    int mode = s_mode;
    for (int i = tid; i < BB*NCH; i += 256) {
        float m;
        if (mode == 2)      m = (((const float*)mptr)[i] != 0.f) ? 1.f : 0.f;
        else if (mode == 1) m = (((const int*)mptr)[i]   != 0)   ? 1.f : 0.f;
        else                m = (((const unsigned char*)mptr)[i] != 0) ? 1.f : 0.f;
        g_maskf[i] = m;
    }
}

// ---------------- basis init: B^T [t][k], bf16 hi/lo split ----------------
__global__ void init_basis_kernel() {
    int idx = blockIdx.x * blockDim.x + threadIdx.x;   // 128*256
    if (idx < DM) g_zbias[idx] = 0.f;
    if (idx >= HCOLS*KPAD) return;
    int t = idx >> 8;          // column 0..127
    int n = idx & 255;         // sample 0..255
    float v = 0.f;
    if (n < 250) {
        if (t < NBINS) {
            int k = t + 2;
            int ph = (k * n) % 500;
            v = (float)cos((2.0 * M_PI / 500.0) * (double)ph);
        } else if (t < 2*NBINS) {
            int k = (t - NBINS) + 2;
            int ph = (k * n) % 500;
            v = (float)(-sin((2.0 * M_PI / 500.0) * (double)ph));
        } else if (t == 116) {
            v = 1.f;
        } else if (t == 117) {
            v = (n & 1) ? -1.f : 1.f;
        }
    }
    __nv_bfloat16 hi = __float2bfloat16(v);
    g_bh[idx] = hi;
    g_bl[idx] = __float2bfloat16(v - __bfloat162float(hi));
}

// ---------------- x split to bf16 hi/lo + per-block energy ----------------
__global__ void xsplit_energy_kernel(const float* __restrict__ x) {
    int gw   = (blockIdx.x * blockDim.x + threadIdx.x) >> 5;
    int lane = threadIdx.x & 31;
    if (gw >= NROWS_A) return;
    const float* p = x + (size_t)gw * 250;
    __nv_bfloat16* ph = g_xh + (size_t)gw * KPAD;
    __nv_bfloat16* pl = g_xl + (size_t)gw * KPAD;
    float s = 0.f;
    #pragma unroll
    for (int j = 0; j < 8; j++) {
        int i = lane + j * 32;
        float v = (i < 250) ? p[i] : 0.f;
        s = fmaf(v, v, s);
        __nv_bfloat16 hi = __float2bfloat16(v);
        ph[i] = hi;
        pl[i] = __float2bfloat16(v - __bfloat162float(hi));
    }
    #pragma unroll
    for (int off = 16; off; off >>= 1) s += __shfl_down_sync(0xffffffffu, s, off);
    if (lane == 0) g_E[gw] = s;
}

// ---------------- bf16 3-pass split MMA GEMM (DFT) ------------------------
// CTA tile 128x128, BK=32, 256 threads = 8 warps (2m x 4n), warp tile 64x32.
#define MM_BUF   32768
#define MM_SMEM  (2*MM_BUF + 1024)

__global__ void __launch_bounds__(256, 2)
mma3_kernel(const __nv_bfloat16* __restrict__ Ah,
            const __nv_bfloat16* __restrict__ Al,
            const __nv_bfloat16* __restrict__ Bh,
            const __nv_bfloat16* __restrict__ Bl,
            float* __restrict__ C,
            const float* __restrict__ bias,
            int ldA, int ldB, int ldC, int ktiles)   // ktiles = K/32
{
    extern __shared__ char sm[];
    uint32_t su = smem_u32(sm);
    float* biasS = (float*)(sm + 2*MM_BUF);

    int tid  = threadIdx.x;
    int wid  = tid >> 5;
    int lane = tid & 31;
    int m0   = blockIdx.y * 128;
    int n0   = blockIdx.x * 128;

    for (int i = tid; i < 128; i += 256) biasS[i] = bias[n0 + i];

    int wm = wid & 1;
    int wn = wid >> 1;

    float acc[4][4][4];
    #pragma unroll
    for (int mi = 0; mi < 4; mi++)
        #pragma unroll
        for (int ni = 0; ni < 4; ni++)
            #pragma unroll
            for (int q = 0; q < 4; q++) acc[mi][ni][q] = 0.f;

    int aRow = lane & 15;
    int aKb  = (lane >> 4) << 4;
    int bRow = lane & 7;
    int bKb  = ((lane >> 3) & 1) << 4;

    auto load_stage = [&](int kt, int buf) {
        int k0 = kt * 32;
        uint32_t base = su + (uint32_t)buf * MM_BUF;
        #pragma unroll
        for (int i = 0; i < 8; i++) {
            int ci  = tid + i * 256;
            int mat = ci >> 9;
            int rem = ci & 511;
            int row = rem >> 2;
            int col = rem & 3;
            uint32_t dst = base + (uint32_t)(mat << 13)
                         + SWZ64((uint32_t)(row * 64 + col * 16));
            const __nv_bfloat16* src;
            if      (mat == 0) src = Ah + (size_t)(m0 + row) * ldA + k0 + col * 8;
            else if (mat == 1) src = Al + (size_t)(m0 + row) * ldA + k0 + col * 8;
            else if (mat == 2) src = Bh + (size_t)(n0 + row) * ldB + k0 + col * 8;
            else               src = Bl + (size_t)(n0 + row) * ldB + k0 + col * 8;
            CP_ASYNC16(dst, src);
        }
        CP_COMMIT();
    };

    load_stage(0, 0);

    for (int kt = 0; kt < ktiles; kt++) {
        if (kt + 1 < ktiles) {
            load_stage(kt + 1, (kt + 1) & 1);
            CP_WAIT1();
        } else {
            CP_WAIT0();
        }
        __syncthreads();

        uint32_t base = su + (uint32_t)(kt & 1) * MM_BUF;
        uint32_t aHT = base;
        uint32_t aLT = base + 8192u;
        uint32_t bHT = base + 16384u;
        uint32_t bLT = base + 24576u;

        #pragma unroll
        for (int k16 = 0; k16 < 2; k16++) {
            uint32_t bh[4][2], bl[4][2];
            #pragma unroll
            for (int ni = 0; ni < 4; ni++) {
                uint32_t off = (uint32_t)((wn * 32 + ni * 8 + bRow) * 64
                                          + k16 * 32 + bKb);
                ldsm_x2(bh[ni][0], bh[ni][1], bHT + SWZ64(off));
                ldsm_x2(bl[ni][0], bl[ni][1], bLT + SWZ64(off));
            }
            uint32_t a[4][4];
            #pragma unroll
            for (int mi = 0; mi < 4; mi++) {
                uint32_t off = (uint32_t)((wm * 64 + mi * 16 + aRow) * 64
                                          + k16 * 32 + aKb);
                ldsm_x4(a[mi][0], a[mi][1], a[mi][2], a[mi][3], aHT + SWZ64(off));
            }
            #pragma unroll
            for (int mi = 0; mi < 4; mi++)
                #pragma unroll
                for (int ni = 0; ni < 4; ni++)
                    mma_bf16(acc[mi][ni], a[mi], bh[ni]);
            #pragma unroll
            for (int mi = 0; mi < 4; mi++)
                #pragma unroll
                for (int ni = 0; ni < 4; ni++)
                    mma_bf16(acc[mi][ni], a[mi], bl[ni]);
            #pragma unroll
            for (int mi = 0; mi < 4; mi++) {
                uint32_t off = (uint32_t)((wm * 64 + mi * 16 + aRow) * 64
                                          + k16 * 32 + aKb);
                ldsm_x4(a[mi][0], a[mi][1], a[mi][2], a[mi][3], aLT + SWZ64(off));
            }
            #pragma unroll
            for (int mi = 0; mi < 4; mi++)
                #pragma unroll
                for (int ni = 0; ni < 4; ni++)
                    mma_bf16(acc[mi][ni], a[mi], bh[ni]);
        }
        __syncthreads();
    }

    int rql = lane >> 2;
    int cql = (lane & 3) * 2;
    #pragma unroll
    for (int mi = 0; mi < 4; mi++) {
        #pragma unroll
        for (int ni = 0; ni < 4; ni++) {
            int r0 = m0 + wm * 64 + mi * 16 + rql;
            int c0 = n0 + wn * 32 + ni * 8 + cql;
            int cl = wn * 32 + ni * 8 + cql;
            float2 v0 = make_float2(acc[mi][ni][0] + biasS[cl],
                                    acc[mi][ni][1] + biasS[cl + 1]);
            float2 v1 = make_float2(acc[mi][ni][2] + biasS[cl],
                                    acc[mi][ni][3] + biasS[cl + 1]);
            *((float2*)(C + (size_t)r0 * ldC + c0)) = v0;
            *((float2*)(C + (size_t)(r0 + 8) * ldC + c0)) = v1;
        }
    }
}

// ---------------- fp16 GEMM2 + bias + LayerNorm fused ----------------------
// One CTA owns 128 rows x full 512 cols. Loops 4 N-tiles of 128 (BK=32,
// double-buffered), stages z = acc+bias in a 128x512 fp16 smem buffer, then
// does per-row LayerNorm from smem and writes fp32 tokens directly to out.
// smem: zbuf 131072 | stage0 16384 | stage1 16384 | bias 2048 | g 2048 | b 2048
#define G2_ZBUF   0
#define G2_STG    131072
#define G2_STGSZ  16384
#define G2_BIAS   (131072 + 32768)
#define G2_G      (G2_BIAS + 2048)
#define G2_B      (G2_G + 2048)
#define G2_SMEM   (G2_B + 2048)

__global__ void __launch_bounds__(256, 1)
gemm2_ln_kernel(const __half* __restrict__ A,
                const __half* __restrict__ B,
                const float* __restrict__ bias,
                const float* __restrict__ lng,
                const float* __restrict__ lnb,
                float* __restrict__ out)
{
    extern __shared__ char sm[];
    uint32_t su = smem_u32(sm);
    __half* zbuf = (__half*)(sm + G2_ZBUF);
    float* biasS = (float*)(sm + G2_BIAS);
    float* gS    = (float*)(sm + G2_G);
    float* bS    = (float*)(sm + G2_B);

    int tid  = threadIdx.x;
    int wid  = tid >> 5;
    int lane = tid & 31;
    int m0   = blockIdx.x * 128;

    for (int i = tid; i < DM; i += 256) {
        biasS[i] = bias[i];
        gS[i]    = lng[i];
        bS[i]    = lnb[i];
    }

    int wm = wid & 1;
    int wn = wid >> 1;
    int aRow = lane & 15;
    int aKb  = (lane >> 4) << 4;
    int bRow = lane & 7;
    int bKb  = ((lane >> 3) & 1) << 4;
    int rql = lane >> 2;
    int cql = (lane & 3) * 2;

    for (int nt = 0; nt < 4; nt++) {
        int n0 = nt * 128;

        float acc[4][4][4];
        #pragma unroll
        for (int mi = 0; mi < 4; mi++)
            #pragma unroll
            for (int ni = 0; ni < 4; ni++)
                #pragma unroll
                for (int q = 0; q < 4; q++) acc[mi][ni][q] = 0.f;

        auto load_stage = [&](int kt, int buf) {
            int k0 = kt * 32;
            uint32_t base = su + G2_STG + (uint32_t)buf * G2_STGSZ;
            #pragma unroll
            for (int i = 0; i < 4; i++) {
                int ci  = tid + i * 256;
                int mat = ci >> 9;              // 0=a 1=b
                int rem = ci & 511;
                int row = rem >> 2;
                int col = rem & 3;
                uint32_t dst = base + (uint32_t)(mat << 13)
                             + SWZ64((uint32_t)(row * 64 + col * 16));
                const __half* src;
                if (mat == 0) src = A + (size_t)(m0 + row) * DM + k0 + col * 8;
                else          src = B + (size_t)(n0 + row) * DM + k0 + col * 8;
                CP_ASYNC16(dst, src);
            }
            CP_COMMIT();
        };

        load_stage(0, 0);

        for (int kt = 0; kt < DM/32; kt++) {
            if (kt + 1 < DM/32) {
                load_stage(kt + 1, (kt + 1) & 1);
                CP_WAIT1();
            } else {
                CP_WAIT0();
            }
            __syncthreads();

            uint32_t base = su + G2_STG + (uint32_t)(kt & 1) * G2_STGSZ;
            uint32_t aT = base;
            uint32_t bT = base + 8192u;

            #pragma unroll
            for (int k16 = 0; k16 < 2; k16++) {
                uint32_t b[4][2];
                #pragma unroll
                for (int ni = 0; ni < 4; ni++) {
                    uint32_t off = (uint32_t)((wn * 32 + ni * 8 + bRow) * 64
                                              + k16 * 32 + bKb);
                    ldsm_x2(b[ni][0], b[ni][1], bT + SWZ64(off));
                }
                uint32_t a[4][4];
                #pragma unroll
                for (int mi = 0; mi < 4; mi++) {
                    uint32_t off = (uint32_t)((wm * 64 + mi * 16 + aRow) * 64
                                              + k16 * 32 + aKb);
                    ldsm_x4(a[mi][0], a[mi][1], a[mi][2], a[mi][3], aT + SWZ64(off));
                }
                #pragma unroll
                for (int mi = 0; mi < 4; mi++)
                    #pragma unroll
                    for (int ni = 0; ni < 4; ni++)
                        mma_f16(acc[mi][ni], a[mi], b[ni]);
            }
            __syncthreads();
        }

        // stage z = acc + bias into fp16 zbuf
        #pragma unroll
        for (int mi = 0; mi < 4; mi++) {
            #pragma unroll
            for (int ni = 0; ni < 4; ni++) {
                int r0 = wm * 64 + mi * 16 + rql;
                int c0 = n0 + wn * 32 + ni * 8 + cql;
                __half2 z0 = __floats2half2_rn(acc[mi][ni][0] + biasS[c0],
                                               acc[mi][ni][1] + biasS[c0 + 1]);
                __half2 z1 = __floats2half2_rn(acc[mi][ni][2] + biasS[c0],
                                               acc[mi][ni][3] + biasS[c0 + 1]);
                *((__half2*)(zbuf + (size_t)r0 * DM + c0)) = z0;
                *((__half2*)(zbuf + (size_t)(r0 + 8) * DM + c0)) = z1;
            }
        }
        __syncthreads();
    }

    // LayerNorm: warp w handles rows w, w+8, ..., w+120
    for (int i = 0; i < 16; i++) {
        int r = wid + i * 8;
        const __half2* zrow = (const __half2*)(zbuf + (size_t)r * DM);
        float s = 0.f, ss = 0.f;
        #pragma unroll
        for (int j = 0; j < 8; j++) {
            float2 v = __half22float2(zrow[lane + 32 * j]);
            s  += v.x + v.y;
            ss += v.x * v.x + v.y * v.y;
        }
        #pragma unroll
        for (int off = 16; off; off >>= 1) {
            s  += __shfl_xor_sync(0xffffffffu, s,  off);
            ss += __shfl_xor_sync(0xffffffffu, ss, off);
        }
        float mu  = s * (1.f / DM);
        float var = ss * (1.f / DM) - mu * mu;
        float rs  = rsqrtf(var + LN_EPS);

        float* orow = out + (size_t)(m0 + r) * DM;
        #pragma unroll
        for (int j = 0; j < 8; j++) {
            int h2i = lane + 32 * j;
            float2 v = __half22float2(zrow[h2i]);
            int c0 = h2i * 2;
            float2 o;
            o.x = (v.x - mu) * rs * gS[c0]     + bS[c0];
            o.y = (v.y - mu) * rs * gS[c0 + 1] + bS[c0 + 1];
            *((float2*)(orow + c0)) = o;
        }
    }
}

// ---------------- generic fp32 SGEMM (desc MLPs only) ----------------
__device__ __forceinline__ float gelu_exact(float x) {
    return 0.5f * x * (1.f + erff(x * 0.70710678118654752f));
}

__global__ void sgemm_bias_act(const float* __restrict__ A,
                               const float* __restrict__ Bm,
                               const float* __restrict__ bias,
                               float* __restrict__ C,
                               int M, int N, int K, int act)
{
    const int BMt = 128, BNt = 128, BKt = 16;
    __shared__ __align__(16) float As[BKt][BMt];
    __shared__ __align__(16) float Bs[BKt][BNt];

    int tid = threadIdx.x;
    int m0 = blockIdx.y * BMt;
    int n0 = blockIdx.x * BNt;
    int ty = tid >> 4;
    int tx = tid & 15;

    float acc[8][8];
    #pragma unroll
    for (int i = 0; i < 8; i++)
        #pragma unroll
        for (int j = 0; j < 8; j++) acc[i][j] = 0.f;

    for (int k0 = 0; k0 < K; k0 += BKt) {
        #pragma unroll
        for (int i = 0; i < 8; i++) {
            int idx = tid + i * 256;
            int ar = idx >> 4;
            int ac = idx & 15;
            int gm = m0 + ar, gk = k0 + ac;
            float v = 0.f;
            if (gm < M && gk < K) v = A[(size_t)gm * K + gk];
            As[ac][ar] = v;
        }
        #pragma unroll
        for (int i = 0; i < 8; i++) {
            int idx = tid + i * 256;
            int br = idx >> 7;
            int bc = idx & 127;
            int gk = k0 + br, gn = n0 + bc;
            float v = 0.f;
            if (gk < K && gn < N) v = Bm[(size_t)gk * N + gn];
            Bs[br][bc] = v;
        }
        __syncthreads();
        #pragma unroll
        for (int kk = 0; kk < BKt; kk++) {
            float4 a0 = ((const float4*)As[kk])[ty * 2];
            float4 a1 = ((const float4*)As[kk])[ty * 2 + 1];
            float4 b0 = ((const float4*)Bs[kk])[tx * 2];
            float4 b1 = ((const float4*)Bs[kk])[tx * 2 + 1];
            float a[8] = {a0.x,a0.y,a0.z,a0.w,a1.x,a1.y,a1.z,a1.w};
            float b[8] = {b0.x,b0.y,b0.z,b0.w,b1.x,b1.y,b1.z,b1.w};
            #pragma unroll
            for (int i = 0; i < 8; i++)
                #pragma unroll
                for (int j = 0; j < 8; j++)
                    acc[i][j] = fmaf(a[i], b[j], acc[i][j]);
        }
        __syncthreads();
    }

    #pragma unroll
    for (int i = 0; i < 8; i++) {
        int gm = m0 + ty * 8 + i;
        if (gm >= M) continue;
        #pragma unroll
        for (int j = 0; j < 8; j++) {
            int gn = n0 + tx * 8 + j;
            if (gn >= N) continue;
            float v = acc[i][j] + bias[gn];
            if (act) v = gelu_exact(v);
            C[(size_t)gm * N + gn] = v;
        }
    }
}

// ---------------- stage B: spectral features per (b,w,c) -------------------
__global__ void stageB_kernel(const float* __restrict__ sensor_pos)
{
    int gw   = (blockIdx.x * blockDim.x + threadIdx.x) >> 5;
    int lane = threadIdx.x & 31;
    if (gw >= NTOK) return;

    int b   = gw / (NW * NCH);
    int rem = gw % (NW * NCH);
    int w   = rem / NCH;
    int c   = rem % NCH;
    int bcn = b * NCH + c;

    const float* H1 = g_H + ((size_t)(bcn * NBLK + w)) * HCOLS;
    const float* H2 = H1 + HCOLS;

    float s0 = 0.f, s1 = 0.f, s2 = 0.f, s3 = 0.f;
    float sa = 0.f, saf = 0.f, pmax = 0.f;
    float sg = (lane & 1) ? -1.f : 1.f;

    #pragma unroll
    for (int rep = 0; rep < 2; rep++) {
        int t = lane + rep * 32;
        if (t < NBINS) {
            float cr1 = H1[t],         ci1 = H1[NBINS + t];
            float cr2 = H2[t],         ci2 = H2[NBINS + t];
            float xr = cr1 + sg * cr2;
            float xi = ci1 + sg * ci2;
            float p  = xr * xr + xi * xi;
            int k = t + 2;
            if      (k <= 7)  s0 += p;
            else if (k <= 15) s1 += p;
            else if (k <= 25) s2 += p;
            else              s3 += p;
            if (k >= 14 && k <= 27) {
                sa  += p;
                saf += p * (0.5f * (float)k);
                pmax = fmaxf(pmax, p);
            }
        }
    }
    #pragma unroll
    for (int off = 16; off; off >>= 1) {
        s0  += __shfl_down_sync(0xffffffffu, s0,  off);
        s1  += __shfl_down_sync(0xffffffffu, s1,  off);
        s2  += __shfl_down_sync(0xffffffffu, s2,  off);
        s3  += __shfl_down_sync(0xffffffffu, s3,  off);
        sa  += __shfl_down_sync(0xffffffffu, sa,  off);
        saf += __shfl_down_sync(0xffffffffu, saf, off);
        pmax = fmaxf(pmax, __shfl_down_sync(0xffffffffu, pmax, off));
    }

    if (lane == 0) {
        float m = g_maskf[bcn];
        float su  = H1[116] + H2[116];
        float alt = H1[117] + H2[117];
        int   rA  = bcn * NBLK + w;
        float e   = g_E[rA] + g_E[rA + 1];
        float Ec  = fmaxf(e - su * su * (1.f / 500.f), 0.f);
        float sumsq = 0.5f * (500.f * Ec + alt * alt);
        float pm  = m * sumsq * (1.f / 251.f) + EPSc;

        float bp0 = m * s0 * (1.f / 6.f)  + EPSc;
        float bp1 = m * s1 * (1.f / 8.f)  + EPSc;
        float bp2 = m * s2 * (1.f / 10.f) + EPSc;
        float bp3 = m * s3 * (1.f / 34.f) + EPSc;
        float total = fmaxf(bp0 + bp1 + bp2 + bp3, EPSc);

        float asum = fmaxf(m * sa + 14.f * EPSc, EPSc);
        float af   = m * saf + 143.5f * EPSc;
        float pkf  = af / asum;
        float amax = m * pmax + EPSc;
        float score = amax / fmaxf(pm, EPSc);
        float py = sensor_pos[bcn * 2 + 1];

        float* f = g_feat + (size_t)gw * 15;
        f[0] = logf(bp0); f[1] = logf(bp1); f[2] = logf(bp2); f[3] = logf(bp3);
        f[4] = bp0 / total; f[5] = bp1 / total; f[6] = bp2 / total; f[7] = bp3 / total;
        f[12] = pkf; f[13] = score; f[14] = py;
        *((float4*)(g_bp + (size_t)gw * 4)) = make_float4(bp0, bp1, bp2, bp3);
    }
}

// ---------------- stage C: channel reductions, desc, topo_dev --------------
__global__ void stageC_kernel(const float* __restrict__ sensor_pos)
{
    __shared__ float red[17][65];
    __shared__ float blog[4];
    int bw = blockIdx.x;
    int b  = bw / NW;
    int c  = threadIdx.x;
    int g  = bw * NCH + c;
    int bcn = b * NCH + c;

    float4 bp4 = *((const float4*)(g_bp + (size_t)g * 4));
    float bp[4] = {bp4.x, bp4.y, bp4.z, bp4.w};
    float m  = g_maskf[bcn];
    float px = sensor_pos[bcn * 2 + 0];
    float py = sensor_pos[bcn * 2 + 1];
    float total = fmaxf(bp[0] + bp[1] + bp[2] + bp[3], EPSc);
    float alpha = bp[2];

    float L = (px < -0.02f && m > 0.f) ? 1.f : 0.f;
    float R = (px >  0.02f && m > 0.f) ? 1.f : 0.f;
    float P = (py < -0.02f && m > 0.f) ? 1.f : 0.f;
    float A = (py >  0.02f && m > 0.f) ? 1.f : 0.f;

    red[0][c] = m;
    red[1][c] = m * bp[0];  red[2][c] = m * bp[1];
    red[3][c] = m * bp[2];  red[4][c] = m * bp[3];
    red[5][c] = m * bp[0] / total;  red[6][c] = m * bp[1] / total;
    red[7][c] = m * bp[2] / total;  red[8][c] = m * bp[3] / total;
    red[9][c]  = alpha * L;  red[10][c] = L;
    red[11][c] = alpha * R;  red[12][c] = R;
    red[13][c] = alpha * P;  red[14][c] = P;
    red[15][c] = alpha * A;  red[16][c] = A;
    __syncthreads();

    for (int off = 32; off >= 1; off >>= 1) {
        if (c < off) {
            #pragma unroll
            for (int q = 0; q < 17; q++) red[q][c] += red[q][c + off];
        }
        __syncthreads();
    }

    if (c == 0) {
        float cnt = fmaxf(red[0][0], 1.f);
        float cm[4], brm[4];
        #pragma unroll
        for (int i = 0; i < 4; i++) {
            cm[i]  = red[1 + i][0] / cnt;
            brm[i] = red[5 + i][0] / cnt;
        }
        float Lm = red[9][0]  / fmaxf(red[10][0], 1.f);
        float Rm = red[11][0] / fmaxf(red[12][0], 1.f);
        float Pm = red[13][0] / fmaxf(red[14][0], 1.f);
        float Am = red[15][0] / fmaxf(red[16][0], 1.f);
        float asym = (Lm - Rm) / fmaxf(Lm + Rm + EPSc, EPSc);
        float ap   = (Pm - Am) / fmaxf(Pm + Am + EPSc, EPSc);
        bool support = (red[16][0] > 0.f) && (red[14][0] > 0.f);
        if (!support) ap = 0.f;

        float* d = g_desc + (size_t)bw * 11;
        #pragma unroll
        for (int i = 0; i < 4; i++) {
            float bl = logf(fmaxf(cm[i], EPSc));
            d[i] = bl;
            d[4 + i] = brm[i];
            blog[i] = bl;
        }
        d[8] = asym; d[9] = ap; d[10] = brm[0] + brm[1];
    }
    __syncthreads();

    float* f = g_feat + (size_t)g * 15;
    #pragma unroll
    for (int i = 0; i < 4; i++)
        f[8 + i] = logf(bp[i]) - blog[i];
}

// ---------------- W2 transpose -> fp16 ----------------
__global__ void w2split_kernel(const float* __restrict__ W2) {
    int idx = blockIdx.x * blockDim.x + threadIdx.x;   // 512*512
    int n = idx >> 9;
    int k = idx & 511;
    float v = W2[(size_t)k * DM + n];
    g_wh[idx] = __float2half(v);
}

// ---------------- GEMM1 fused: hid = gelu(feat @ W1 + b1) -> fp16 ---------
__global__ void gemm1_fused_kernel(const float* __restrict__ W1,
                                   const float* __restrict__ b1)
{
    __shared__ float W1s[15 * DM];
    __shared__ float b1s[DM];
    int tid = threadIdx.x;                 // 256
    for (int i = tid; i < 15 * DM; i += 256) W1s[i] = W1[i];
    for (int i = tid; i < DM; i += 256)      b1s[i] = b1[i];
    __syncthreads();

    int warp = tid >> 5, lane = tid & 31;
    int row0 = (blockIdx.x * 8 + warp) * 32;

    for (int rr = 0; rr < 32; rr++) {
        int row = row0 + rr;
        const float* fr = g_feat + (size_t)row * 15;
        float a[15];
        #pragma unroll
        for (int k = 0; k < 15; k++) a[k] = fr[k];
        #pragma unroll 4
        for (int i = 0; i < 16; i++) {
            int n = lane + i * 32;
            float acc = b1s[n];
            #pragma unroll
            for (int k = 0; k < 15; k++)
                acc = fmaf(a[k], W1s[k * DM + n], acc);
            float gv = gelu_exact(acc);
            g_hh[(size_t)row * DM + n] = __float2half(gv);
        }
    }
}

// ---------------- launch ----------------
static void* symaddr(const void* s) {
    void* p = nullptr;
    cudaGetSymbolAddress(&p, s);
    return p;
}

extern "C" void kernel_launch(void* const* d_in, const int* in_sizes, int n_in,
                              void* d_out, int out_size)
{
    const float* x    = (const float*)d_in[0];
    const float* spos = (const float*)d_in[1];
    const void*  smask = (const void*)d_in[2];
    const float* Wf1 = (const float*)d_in[3];
    const float* bf1 = (const float*)d_in[4];
    const float* Wf2 = (const float*)d_in[5];
    const float* bf2 = (const float*)d_in[6];
    const float* lng = (const float*)d_in[7];
    const float* lnb = (const float*)d_in[8];
    const float* Wd1 = (const float*)d_in[9];
    const float* bd1 = (const float*)d_in[10];
    const float* Wd2 = (const float*)d_in[11];
    const float* bd2 = (const float*)d_in[12];
    float* out = (float*)d_out;

    __nv_bfloat16* xh = (__nv_bfloat16*)symaddr(g_xh);
    __nv_bfloat16* xl = (__nv_bfloat16*)symaddr(g_xl);
    __nv_bfloat16* bh = (__nv_bfloat16*)symaddr(g_bh);
    __nv_bfloat16* bl = (__nv_bfloat16*)symaddr(g_bl);
    __half* hh = (__half*)symaddr(g_hh);
    __half* wh = (__half*)symaddr(g_wh);
    float* zbias = (float*)symaddr(g_zbias);
    float* H     = (float*)symaddr(g_H);
    float* desc  = (float*)symaddr(g_desc);
    float* hd    = (float*)symaddr(g_hd);

    static int attr_set = 0;
    if (!attr_set) {
        cudaFuncSetAttribute(mma3_kernel,
                             cudaFuncAttributeMaxDynamicSharedMemorySize,
                             MM_SMEM);
        cudaFuncSetAttribute(gemm2_ln_kernel,
                             cudaFuncAttributeMaxDynamicSharedMemorySize,
                             G2_SMEM);
        attr_set = 1;
    }

    // 0) mask dtype detect + convert
    mask_convert_kernel<<<1, 256>>>(smask);
    // 1) basis (transposed, split)
    init_basis_kernel<<<(HCOLS*KPAD + 255)/256, 256>>>();
    // 2) x split to bf16 hi/lo + per-block energy (single pass over x)
    xsplit_energy_kernel<<<NROWS_A/8, 256>>>(x);
    // 3) half-block DFT on tensor cores (bf16 3-pass): -> g_H
    mma3_kernel<<<dim3(1, NROWS_A/128), 256, MM_SMEM>>>(
        xh, xl, bh, bl, H, zbias, KPAD, KPAD, HCOLS, KPAD/32);
    // 4) spectral features per token
    stageB_kernel<<<NTOK/8, 256>>>(spos);
    // 5) channel reductions + desc + topo_dev
    stageC_kernel<<<NBW, 64>>>(spos);
    // 6) W2 transpose -> fp16 (tiny)
    w2split_kernel<<<(DM*DM)/256, 256>>>(Wf2);
    // 7) token MLP layer 1 fused: gelu(feat W1 + b1) -> fp16
    gemm1_fused_kernel<<<NTOK/256, 256>>>(Wf1, bf1);
    // 8) token MLP layer 2 + bias + LayerNorm fused -> out (tokens)
    gemm2_ln_kernel<<<NTOK/128, 256, G2_SMEM>>>(hh, wh, bf2, lng, lnb, out);
    // 9) desc MLP layer 1
    sgemm_bias_act<<<dim3(DM/128, (NBW + 127)/128), 256>>>(desc, Wd1, bd1, hd,
                                                           NBW, DM, 11, 1);
    // 10) desc MLP layer 2 -> desc output
    sgemm_bias_act<<<dim3(DM/128, (NBW + 127)/128), 256>>>(hd, Wd2, bd2,
                                                           out + TOK_ELEMS,
                                                           NBW, DM, DM, 0);
    (void)in_sizes; (void)n_in; (void)out_size;
}

// round 16
// speedup vs baseline: 1.0876x; 1.0876x over previous
#include <cuda_runtime.h>
#include <cuda_bf16.h>
#include <cuda_fp16.h>
#include <math.h>
#include <stdint.h>

// ---------------- problem constants ----------------
#define BB   16
#define NCH  64
#define TT   15000
#define WS   500
#define STp  250
#define NW   59              // (T-WS)/ST + 1
#define NBLK 60              // half-blocks per channel
#define NBINS 58             // k = 2..59
#define DM   512
#define EPSc 1e-6f
#define LN_EPS 1e-5f

#define NROWS_A   (BB*NCH*NBLK)      // 61440  half-block rows
#define NTOK      (BB*NW*NCH)        // 60416
#define NBW       (BB*NW)            // 944
#define HCOLS     128                // padded H width
#define KPAD      256                // padded DFT K (250 -> 256)
#define TOK_ELEMS (NTOK*DM)

#ifndef M_PI
#define M_PI 3.14159265358979323846
#endif

// ---------------- scratch (static device globals) ----------------
__device__ float g_zbias[DM];
__device__ float g_H[(size_t)NROWS_A*HCOLS];
__device__ float g_E[NROWS_A];
__device__ float g_feat[(size_t)NTOK*15];
__device__ float g_bp[(size_t)NTOK*4];
__device__ float g_desc[(size_t)NBW*11];
__device__ float g_hd[(size_t)NBW*DM];
__device__ float g_maskf[BB*NCH];
// bf16 split operands (DFT, 3-pass)
__device__ __nv_bfloat16 g_xh[(size_t)NROWS_A*KPAD];   // x half-blocks hi
__device__ __nv_bfloat16 g_xl[(size_t)NROWS_A*KPAD];   // x half-blocks lo
__device__ __nv_bfloat16 g_bh[HCOLS*KPAD];             // DFT basis^T hi [t][k]
__device__ __nv_bfloat16 g_bl[HCOLS*KPAD];             // DFT basis^T lo
// fp16 operands (token GEMM2, single pass)
__device__ __half g_hh[(size_t)NTOK*DM];               // fp16(gelu(feat W1 + b1))
__device__ __half g_wh[DM*DM];                         // Wf2^T fp16 [n][k]
__device__ __half g_tokh[(size_t)NTOK*DM];             // fp16 z = hid W2 + b2

// ================= portable PTX helpers (sm_80+ baseline) ==================
__device__ __forceinline__ uint32_t smem_u32(const void* p) {
    uint32_t a;
    asm("{ .reg .u64 t; cvta.to.shared.u64 t, %1; cvt.u32.u64 %0, t; }"
        : "=r"(a) : "l"(p));
    return a;
}

// Swizzle for 64-byte-wide rows (Swizzle<2,4,3>)
#define SWZ64(off)  ((off) ^ (((off) >> 3) & 0x30))

#define CP_ASYNC16(dst, src) \
    asm volatile("cp.async.cg.shared.global [%0], [%1], 16;" :: "r"(dst), "l"(src))
#define CP_COMMIT() asm volatile("cp.async.commit_group;" ::: "memory")
#define CP_WAIT0()  asm volatile("cp.async.wait_group 0;" ::: "memory")
#define CP_WAIT1()  asm volatile("cp.async.wait_group 1;" ::: "memory")

__device__ __forceinline__ void ldsm_x4(uint32_t& r0, uint32_t& r1,
                                        uint32_t& r2, uint32_t& r3, uint32_t addr) {
    asm volatile("ldmatrix.sync.aligned.m8n8.x4.shared.b16 {%0,%1,%2,%3}, [%4];"
                 : "=r"(r0), "=r"(r1), "=r"(r2), "=r"(r3) : "r"(addr));
}
__device__ __forceinline__ void ldsm_x2(uint32_t& r0, uint32_t& r1, uint32_t addr) {
    asm volatile("ldmatrix.sync.aligned.m8n8.x2.shared.b16 {%0,%1}, [%2];"
                 : "=r"(r0), "=r"(r1) : "r"(addr));
}
__device__ __forceinline__ void mma_bf16(float* c, const uint32_t* a, const uint32_t* b) {
    asm volatile(
        "mma.sync.aligned.m16n8k16.row.col.f32.bf16.bf16.f32 "
        "{%0,%1,%2,%3}, {%4,%5,%6,%7}, {%8,%9}, {%0,%1,%2,%3};"
        : "+f"(c[0]), "+f"(c[1]), "+f"(c[2]), "+f"(c[3])
        : "r"(a[0]), "r"(a[1]), "r"(a[2]), "r"(a[3]), "r"(b[0]), "r"(b[1]));
}
__device__ __forceinline__ void mma_f16(float* c, const uint32_t* a, const uint32_t* b) {
    asm volatile(
        "mma.sync.aligned.m16n8k16.row.col.f32.f16.f16.f32 "
        "{%0,%1,%2,%3}, {%4,%5,%6,%7}, {%8,%9}, {%0,%1,%2,%3};"
        : "+f"(c[0]), "+f"(c[1]), "+f"(c[2]), "+f"(c[3])
        : "r"(a[0]), "r"(a[1]), "r"(a[2]), "r"(a[3]), "r"(b[0]), "r"(b[1]));
}

// ---------------- mask dtype detection + conversion ----------------
__global__ void mask_convert_kernel(const void* mptr) {
    __shared__ int s_anyFloat, s_anyHighByte, s_mode;
    int tid = threadIdx.x;
    if (tid == 0) { s_anyFloat = 0; s_anyHighByte = 0; }
    __syncthreads();
    unsigned int w = ((const unsigned int*)mptr)[tid];
    if (w == 0x3F800000u) atomicOr(&s_anyFloat, 1);
    else if ((w & 0xFFFFFF00u) != 0u) atomicOr(&s_anyHighByte, 1);
    __syncthreads();
    if (tid == 0)
        s_mode = s_anyFloat ? 2 : (s_anyHighByte ? 0 : 1);
    __syncthreads();
    int mode = s_mode;
    for (int i = tid; i < BB*NCH; i += 256) {
        float m;
        if (mode == 2)      m = (((const float*)mptr)[i] != 0.f) ? 1.f : 0.f;
        else if (mode == 1) m = (((const int*)mptr)[i]   != 0)   ? 1.f : 0.f;
        else                m = (((const unsigned char*)mptr)[i] != 0) ? 1.f : 0.f;
        g_maskf[i] = m;
    }
}

// ---------------- basis init: B^T [t][k], bf16 hi/lo split ----------------
__global__ void init_basis_kernel() {
    int idx = blockIdx.x * blockDim.x + threadIdx.x;   // 128*256
    if (idx < DM) g_zbias[idx] = 0.f;
    if (idx >= HCOLS*KPAD) return;
    int t = idx >> 8;          // column 0..127
    int n = idx & 255;         // sample 0..255
    float v = 0.f;
    if (n < 250) {
        if (t < NBINS) {
            int k = t + 2;
            int ph = (k * n) % 500;
            v = (float)cos((2.0 * M_PI / 500.0) * (double)ph);
        } else if (t < 2*NBINS) {
            int k = (t - NBINS) + 2;
            int ph = (k * n) % 500;
            v = (float)(-sin((2.0 * M_PI / 500.0) * (double)ph));
        } else if (t == 116) {
            v = 1.f;
        } else if (t == 117) {
            v = (n & 1) ? -1.f : 1.f;
        }
    }
    __nv_bfloat16 hi = __float2bfloat16(v);
    g_bh[idx] = hi;
    g_bl[idx] = __float2bfloat16(v - __bfloat162float(hi));
}

// ---------------- x split to bf16 hi/lo + per-block energy ----------------
__global__ void xsplit_energy_kernel(const float* __restrict__ x) {
    int gw   = (blockIdx.x * blockDim.x + threadIdx.x) >> 5;
    int lane = threadIdx.x & 31;
    if (gw >= NROWS_A) return;
    const float* p = x + (size_t)gw * 250;
    __nv_bfloat16* ph = g_xh + (size_t)gw * KPAD;
    __nv_bfloat16* pl = g_xl + (size_t)gw * KPAD;
    float s = 0.f;
    #pragma unroll
    for (int j = 0; j < 8; j++) {
        int i = lane + j * 32;
        float v = (i < 250) ? p[i] : 0.f;
        s = fmaf(v, v, s);
        __nv_bfloat16 hi = __float2bfloat16(v);
        ph[i] = hi;
        pl[i] = __float2bfloat16(v - __bfloat162float(hi));
    }
    #pragma unroll
    for (int off = 16; off; off >>= 1) s += __shfl_down_sync(0xffffffffu, s, off);
    if (lane == 0) g_E[gw] = s;
}

// ---------------- bf16 3-pass split MMA GEMM (DFT) ------------------------
// CTA tile 128x128, BK=32, 256 threads = 8 warps (2m x 4n), warp tile 64x32.
#define MM_BUF   32768
#define MM_SMEM  (2*MM_BUF + 1024)

__global__ void __launch_bounds__(256, 2)
mma3_kernel(const __nv_bfloat16* __restrict__ Ah,
            const __nv_bfloat16* __restrict__ Al,
            const __nv_bfloat16* __restrict__ Bh,
            const __nv_bfloat16* __restrict__ Bl,
            float* __restrict__ C,
            const float* __restrict__ bias,
            int ldA, int ldB, int ldC, int ktiles)   // ktiles = K/32
{
    extern __shared__ char sm[];
    uint32_t su = smem_u32(sm);
    float* biasS = (float*)(sm + 2*MM_BUF);

    int tid  = threadIdx.x;
    int wid  = tid >> 5;
    int lane = tid & 31;
    int m0   = blockIdx.y * 128;
    int n0   = blockIdx.x * 128;

    for (int i = tid; i < 128; i += 256) biasS[i] = bias[n0 + i];

    int wm = wid & 1;
    int wn = wid >> 1;

    float acc[4][4][4];
    #pragma unroll
    for (int mi = 0; mi < 4; mi++)
        #pragma unroll
        for (int ni = 0; ni < 4; ni++)
            #pragma unroll
            for (int q = 0; q < 4; q++) acc[mi][ni][q] = 0.f;

    int aRow = lane & 15;
    int aKb  = (lane >> 4) << 4;
    int bRow = lane & 7;
    int bKb  = ((lane >> 3) & 1) << 4;

    auto load_stage = [&](int kt, int buf) {
        int k0 = kt * 32;
        uint32_t base = su + (uint32_t)buf * MM_BUF;
        #pragma unroll
        for (int i = 0; i < 8; i++) {
            int ci  = tid + i * 256;
            int mat = ci >> 9;
            int rem = ci & 511;
            int row = rem >> 2;
            int col = rem & 3;
            uint32_t dst = base + (uint32_t)(mat << 13)
                         + SWZ64((uint32_t)(row * 64 + col * 16));
            const __nv_bfloat16* src;
            if      (mat == 0) src = Ah + (size_t)(m0 + row) * ldA + k0 + col * 8;
            else if (mat == 1) src = Al + (size_t)(m0 + row) * ldA + k0 + col * 8;
            else if (mat == 2) src = Bh + (size_t)(n0 + row) * ldB + k0 + col * 8;
            else               src = Bl + (size_t)(n0 + row) * ldB + k0 + col * 8;
            CP_ASYNC16(dst, src);
        }
        CP_COMMIT();
    };

    load_stage(0, 0);

    for (int kt = 0; kt < ktiles; kt++) {
        if (kt + 1 < ktiles) {
            load_stage(kt + 1, (kt + 1) & 1);
            CP_WAIT1();
        } else {
            CP_WAIT0();
        }
        __syncthreads();

        uint32_t base = su + (uint32_t)(kt & 1) * MM_BUF;
        uint32_t aHT = base;
        uint32_t aLT = base + 8192u;
        uint32_t bHT = base + 16384u;
        uint32_t bLT = base + 24576u;

        #pragma unroll
        for (int k16 = 0; k16 < 2; k16++) {
            uint32_t bh[4][2], bl[4][2];
            #pragma unroll
            for (int ni = 0; ni < 4; ni++) {
                uint32_t off = (uint32_t)((wn * 32 + ni * 8 + bRow) * 64
                                          + k16 * 32 + bKb);
                ldsm_x2(bh[ni][0], bh[ni][1], bHT + SWZ64(off));
                ldsm_x2(bl[ni][0], bl[ni][1], bLT + SWZ64(off));
            }
            uint32_t a[4][4];
            #pragma unroll
            for (int mi = 0; mi < 4; mi++) {
                uint32_t off = (uint32_t)((wm * 64 + mi * 16 + aRow) * 64
                                          + k16 * 32 + aKb);
                ldsm_x4(a[mi][0], a[mi][1], a[mi][2], a[mi][3], aHT + SWZ64(off));
            }
            #pragma unroll
            for (int mi = 0; mi < 4; mi++)
                #pragma unroll
                for (int ni = 0; ni < 4; ni++)
                    mma_bf16(acc[mi][ni], a[mi], bh[ni]);
            #pragma unroll
            for (int mi = 0; mi < 4; mi++)
                #pragma unroll
                for (int ni = 0; ni < 4; ni++)
                    mma_bf16(acc[mi][ni], a[mi], bl[ni]);
            #pragma unroll
            for (int mi = 0; mi < 4; mi++) {
                uint32_t off = (uint32_t)((wm * 64 + mi * 16 + aRow) * 64
                                          + k16 * 32 + aKb);
                ldsm_x4(a[mi][0], a[mi][1], a[mi][2], a[mi][3], aLT + SWZ64(off));
            }
            #pragma unroll
            for (int mi = 0; mi < 4; mi++)
                #pragma unroll
                for (int ni = 0; ni < 4; ni++)
                    mma_bf16(acc[mi][ni], a[mi], bh[ni]);
        }
        __syncthreads();
    }

    int rql = lane >> 2;
    int cql = (lane & 3) * 2;
    #pragma unroll
    for (int mi = 0; mi < 4; mi++) {
        #pragma unroll
        for (int ni = 0; ni < 4; ni++) {
            int r0 = m0 + wm * 64 + mi * 16 + rql;
            int c0 = n0 + wn * 32 + ni * 8 + cql;
            int cl = wn * 32 + ni * 8 + cql;
            float2 v0 = make_float2(acc[mi][ni][0] + biasS[cl],
                                    acc[mi][ni][1] + biasS[cl + 1]);
            float2 v1 = make_float2(acc[mi][ni][2] + biasS[cl],
                                    acc[mi][ni][3] + biasS[cl + 1]);
            *((float2*)(C + (size_t)r0 * ldC + c0)) = v0;
            *((float2*)(C + (size_t)(r0 + 8) * ldC + c0)) = v1;
        }
    }
}

// ---------------- fp16 single-pass MMA GEMM (token GEMM2), fp16 out --------
// Z = A * B^T + bias  -> g_tokh (fp16).  CTA tile 128x128, BK=32, 256 thr,
// 8 warps (2m x 4n), warp tile 64x32. Stage: a @0 (8KB), b @8192 -> 16KB.
#define MM2_BUF   16384
#define MM2_SMEM  (2*MM2_BUF + 1024)

__global__ void __launch_bounds__(256, 2)
mma1h_kernel(const __half* __restrict__ A,
             const __half* __restrict__ B,
             __half* __restrict__ Z,
             const float* __restrict__ bias,
             int ldA, int ldB, int ldC, int ktiles)   // ktiles = K/32
{
    extern __shared__ char sm[];
    uint32_t su = smem_u32(sm);
    float* biasS = (float*)(sm + 2*MM2_BUF);

    int tid  = threadIdx.x;
    int wid  = tid >> 5;
    int lane = tid & 31;
    int m0   = blockIdx.y * 128;
    int n0   = blockIdx.x * 128;

    for (int i = tid; i < 128; i += 256) biasS[i] = bias[n0 + i];

    int wm = wid & 1;
    int wn = wid >> 1;

    float acc[4][4][4];
    #pragma unroll
    for (int mi = 0; mi < 4; mi++)
        #pragma unroll
        for (int ni = 0; ni < 4; ni++)
            #pragma unroll
            for (int q = 0; q < 4; q++) acc[mi][ni][q] = 0.f;

    int aRow = lane & 15;
    int aKb  = (lane >> 4) << 4;
    int bRow = lane & 7;
    int bKb  = ((lane >> 3) & 1) << 4;

    auto load_stage = [&](int kt, int buf) {
        int k0 = kt * 32;
        uint32_t base = su + (uint32_t)buf * MM2_BUF;
        #pragma unroll
        for (int i = 0; i < 4; i++) {
            int ci  = tid + i * 256;
            int mat = ci >> 9;              // 0=a 1=b
            int rem = ci & 511;
            int row = rem >> 2;
            int col = rem & 3;
            uint32_t dst = base + (uint32_t)(mat << 13)
                         + SWZ64((uint32_t)(row * 64 + col * 16));
            const __half* src;
            if (mat == 0) src = A + (size_t)(m0 + row) * ldA + k0 + col * 8;
            else          src = B + (size_t)(n0 + row) * ldB + k0 + col * 8;
            CP_ASYNC16(dst, src);
        }
        CP_COMMIT();
    };

    load_stage(0, 0);

    for (int kt = 0; kt < ktiles; kt++) {
        if (kt + 1 < ktiles) {
            load_stage(kt + 1, (kt + 1) & 1);
            CP_WAIT1();
        } else {
            CP_WAIT0();
        }
        __syncthreads();

        uint32_t base = su + (uint32_t)(kt & 1) * MM2_BUF;
        uint32_t aT = base;
        uint32_t bT = base + 8192u;

        #pragma unroll
        for (int k16 = 0; k16 < 2; k16++) {
            uint32_t b[4][2];
            #pragma unroll
            for (int ni = 0; ni < 4; ni++) {
                uint32_t off = (uint32_t)((wn * 32 + ni * 8 + bRow) * 64
                                          + k16 * 32 + bKb);
                ldsm_x2(b[ni][0], b[ni][1], bT + SWZ64(off));
            }
            uint32_t a[4][4];
            #pragma unroll
            for (int mi = 0; mi < 4; mi++) {
                uint32_t off = (uint32_t)((wm * 64 + mi * 16 + aRow) * 64
                                          + k16 * 32 + aKb);
                ldsm_x4(a[mi][0], a[mi][1], a[mi][2], a[mi][3], aT + SWZ64(off));
            }
            #pragma unroll
            for (int mi = 0; mi < 4; mi++)
                #pragma unroll
                for (int ni = 0; ni < 4; ni++)
                    mma_f16(acc[mi][ni], a[mi], b[ni]);
        }
        __syncthreads();
    }

    int rql = lane >> 2;
    int cql = (lane & 3) * 2;
    #pragma unroll
    for (int mi = 0; mi < 4; mi++) {
        #pragma unroll
        for (int ni = 0; ni < 4; ni++) {
            int r0 = m0 + wm * 64 + mi * 16 + rql;
            int c0 = n0 + wn * 32 + ni * 8 + cql;
            int cl = wn * 32 + ni * 8 + cql;
            __half2 z0 = __floats2half2_rn(acc[mi][ni][0] + biasS[cl],
                                           acc[mi][ni][1] + biasS[cl + 1]);
            __half2 z1 = __floats2half2_rn(acc[mi][ni][2] + biasS[cl],
                                           acc[mi][ni][3] + biasS[cl + 1]);
            *((__half2*)(Z + (size_t)r0 * ldC + c0)) = z0;
            *((__half2*)(Z + (size_t)(r0 + 8) * ldC + c0)) = z1;
        }
    }
}

// ---------------- generic fp32 SGEMM (desc MLPs only) ----------------
__device__ __forceinline__ float gelu_exact(float x) {
    return 0.5f * x * (1.f + erff(x * 0.70710678118654752f));
}

__global__ void sgemm_bias_act(const float* __restrict__ A,
                               const float* __restrict__ Bm,
                               const float* __restrict__ bias,
                               float* __restrict__ C,
                               int M, int N, int K, int act)
{
    const int BMt = 128, BNt = 128, BKt = 16;
    __shared__ __align__(16) float As[BKt][BMt];
    __shared__ __align__(16) float Bs[BKt][BNt];

    int tid = threadIdx.x;
    int m0 = blockIdx.y * BMt;
    int n0 = blockIdx.x * BNt;
    int ty = tid >> 4;
    int tx = tid & 15;

    float acc[8][8];
    #pragma unroll
    for (int i = 0; i < 8; i++)
        #pragma unroll
        for (int j = 0; j < 8; j++) acc[i][j] = 0.f;

    for (int k0 = 0; k0 < K; k0 += BKt) {
        #pragma unroll
        for (int i = 0; i < 8; i++) {
            int idx = tid + i * 256;
            int ar = idx >> 4;
            int ac = idx & 15;
            int gm = m0 + ar, gk = k0 + ac;
            float v = 0.f;
            if (gm < M && gk < K) v = A[(size_t)gm * K + gk];
            As[ac][ar] = v;
        }
        #pragma unroll
        for (int i = 0; i < 8; i++) {
            int idx = tid + i * 256;
            int br = idx >> 7;
            int bc = idx & 127;
            int gk = k0 + br, gn = n0 + bc;
            float v = 0.f;
            if (gk < K && gn < N) v = Bm[(size_t)gk * N + gn];
            Bs[br][bc] = v;
        }
        __syncthreads();
        #pragma unroll
        for (int kk = 0; kk < BKt; kk++) {
            float4 a0 = ((const float4*)As[kk])[ty * 2];
            float4 a1 = ((const float4*)As[kk])[ty * 2 + 1];
            float4 b0 = ((const float4*)Bs[kk])[tx * 2];
            float4 b1 = ((const float4*)Bs[kk])[tx * 2 + 1];
            float a[8] = {a0.x,a0.y,a0.z,a0.w,a1.x,a1.y,a1.z,a1.w};
            float b[8] = {b0.x,b0.y,b0.z,b0.w,b1.x,b1.y,b1.z,b1.w};
            #pragma unroll
            for (int i = 0; i < 8; i++)
                #pragma unroll
                for (int j = 0; j < 8; j++)
                    acc[i][j] = fmaf(a[i], b[j], acc[i][j]);
        }
        __syncthreads();
    }

    #pragma unroll
    for (int i = 0; i < 8; i++) {
        int gm = m0 + ty * 8 + i;
        if (gm >= M) continue;
        #pragma unroll
        for (int j = 0; j < 8; j++) {
            int gn = n0 + tx * 8 + j;
            if (gn >= N) continue;
            float v = acc[i][j] + bias[gn];
            if (act) v = gelu_exact(v);
            C[(size_t)gm * N + gn] = v;
        }
    }
}

// ---------------- stage B: spectral features per (b,w,c) -------------------
__global__ void stageB_kernel(const float* __restrict__ sensor_pos)
{
    int gw   = (blockIdx.x * blockDim.x + threadIdx.x) >> 5;
    int lane = threadIdx.x & 31;
    if (gw >= NTOK) return;

    int b   = gw / (NW * NCH);
    int rem = gw % (NW * NCH);
    int w   = rem / NCH;
    int c   = rem % NCH;
    int bcn = b * NCH + c;

    const float* H1 = g_H + ((size_t)(bcn * NBLK + w)) * HCOLS;
    const float* H2 = H1 + HCOLS;

    float s0 = 0.f, s1 = 0.f, s2 = 0.f, s3 = 0.f;
    float sa = 0.f, saf = 0.f, pmax = 0.f;
    float sg = (lane & 1) ? -1.f : 1.f;

    #pragma unroll
    for (int rep = 0; rep < 2; rep++) {
        int t = lane + rep * 32;
        if (t < NBINS) {
            float cr1 = H1[t],         ci1 = H1[NBINS + t];
            float cr2 = H2[t],         ci2 = H2[NBINS + t];
            float xr = cr1 + sg * cr2;
            float xi = ci1 + sg * ci2;
            float p  = xr * xr + xi * xi;
            int k = t + 2;
            if      (k <= 7)  s0 += p;
            else if (k <= 15) s1 += p;
            else if (k <= 25) s2 += p;
            else              s3 += p;
            if (k >= 14 && k <= 27) {
                sa  += p;
                saf += p * (0.5f * (float)k);
                pmax = fmaxf(pmax, p);
            }
        }
    }
    #pragma unroll
    for (int off = 16; off; off >>= 1) {
        s0  += __shfl_down_sync(0xffffffffu, s0,  off);
        s1  += __shfl_down_sync(0xffffffffu, s1,  off);
        s2  += __shfl_down_sync(0xffffffffu, s2,  off);
        s3  += __shfl_down_sync(0xffffffffu, s3,  off);
        sa  += __shfl_down_sync(0xffffffffu, sa,  off);
        saf += __shfl_down_sync(0xffffffffu, saf, off);
        pmax = fmaxf(pmax, __shfl_down_sync(0xffffffffu, pmax, off));
    }

    if (lane == 0) {
        float m = g_maskf[bcn];
        float su  = H1[116] + H2[116];
        float alt = H1[117] + H2[117];
        int   rA  = bcn * NBLK + w;
        float e   = g_E[rA] + g_E[rA + 1];
        float Ec  = fmaxf(e - su * su * (1.f / 500.f), 0.f);
        float sumsq = 0.5f * (500.f * Ec + alt * alt);
        float pm  = m * sumsq * (1.f / 251.f) + EPSc;

        float bp0 = m * s0 * (1.f / 6.f)  + EPSc;
        float bp1 = m * s1 * (1.f / 8.f)  + EPSc;
        float bp2 = m * s2 * (1.f / 10.f) + EPSc;
        float bp3 = m * s3 * (1.f / 34.f) + EPSc;
        float total = fmaxf(bp0 + bp1 + bp2 + bp3, EPSc);

        float asum = fmaxf(m * sa + 14.f * EPSc, EPSc);
        float af   = m * saf + 143.5f * EPSc;
        float pkf  = af / asum;
        float amax = m * pmax + EPSc;
        float score = amax / fmaxf(pm, EPSc);
        float py = sensor_pos[bcn * 2 + 1];

        float* f = g_feat + (size_t)gw * 15;
        f[0] = logf(bp0); f[1] = logf(bp1); f[2] = logf(bp2); f[3] = logf(bp3);
        f[4] = bp0 / total; f[5] = bp1 / total; f[6] = bp2 / total; f[7] = bp3 / total;
        f[12] = pkf; f[13] = score; f[14] = py;
        *((float4*)(g_bp + (size_t)gw * 4)) = make_float4(bp0, bp1, bp2, bp3);
    }
}

// ---------------- stage C: channel reductions, desc, topo_dev --------------
__global__ void stageC_kernel(const float* __restrict__ sensor_pos)
{
    __shared__ float red[17][65];
    __shared__ float blog[4];
    int bw = blockIdx.x;
    int b  = bw / NW;
    int c  = threadIdx.x;
    int g  = bw * NCH + c;
    int bcn = b * NCH + c;

    float4 bp4 = *((const float4*)(g_bp + (size_t)g * 4));
    float bp[4] = {bp4.x, bp4.y, bp4.z, bp4.w};
    float m  = g_maskf[bcn];
    float px = sensor_pos[bcn * 2 + 0];
    float py = sensor_pos[bcn * 2 + 1];
    float total = fmaxf(bp[0] + bp[1] + bp[2] + bp[3], EPSc);
    float alpha = bp[2];

    float L = (px < -0.02f && m > 0.f) ? 1.f : 0.f;
    float R = (px >  0.02f && m > 0.f) ? 1.f : 0.f;
    float P = (py < -0.02f && m > 0.f) ? 1.f : 0.f;
    float A = (py >  0.02f && m > 0.f) ? 1.f : 0.f;

    red[0][c] = m;
    red[1][c] = m * bp[0];  red[2][c] = m * bp[1];
    red[3][c] = m * bp[2];  red[4][c] = m * bp[3];
    red[5][c] = m * bp[0] / total;  red[6][c] = m * bp[1] / total;
    red[7][c] = m * bp[2] / total;  red[8][c] = m * bp[3] / total;
    red[9][c]  = alpha * L;  red[10][c] = L;
    red[11][c] = alpha * R;  red[12][c] = R;
    red[13][c] = alpha * P;  red[14][c] = P;
    red[15][c] = alpha * A;  red[16][c] = A;
    __syncthreads();

    for (int off = 32; off >= 1; off >>= 1) {
        if (c < off) {
            #pragma unroll
            for (int q = 0; q < 17; q++) red[q][c] += red[q][c + off];
        }
        __syncthreads();
    }

    if (c == 0) {
        float cnt = fmaxf(red[0][0], 1.f);
        float cm[4], brm[4];
        #pragma unroll
        for (int i = 0; i < 4; i++) {
            cm[i]  = red[1 + i][0] / cnt;
            brm[i] = red[5 + i][0] / cnt;
        }
        float Lm = red[9][0]  / fmaxf(red[10][0], 1.f);
        float Rm = red[11][0] / fmaxf(red[12][0], 1.f);
        float Pm = red[13][0] / fmaxf(red[14][0], 1.f);
        float Am = red[15][0] / fmaxf(red[16][0], 1.f);
        float asym = (Lm - Rm) / fmaxf(Lm + Rm + EPSc, EPSc);
        float ap   = (Pm - Am) / fmaxf(Pm + Am + EPSc, EPSc);
        bool support = (red[16][0] > 0.f) && (red[14][0] > 0.f);
        if (!support) ap = 0.f;

        float* d = g_desc + (size_t)bw * 11;
        #pragma unroll
        for (int i = 0; i < 4; i++) {
            float bl = logf(fmaxf(cm[i], EPSc));
            d[i] = bl;
            d[4 + i] = brm[i];
            blog[i] = bl;
        }
        d[8] = asym; d[9] = ap; d[10] = brm[0] + brm[1];
    }
    __syncthreads();

    float* f = g_feat + (size_t)g * 15;
    #pragma unroll
    for (int i = 0; i < 4; i++)
        f[8 + i] = logf(bp[i]) - blog[i];
}

// ---------------- W2 transpose -> fp16 ----------------
__global__ void w2split_kernel(const float* __restrict__ W2) {
    int idx = blockIdx.x * blockDim.x + threadIdx.x;   // 512*512
    int n = idx >> 9;
    int k = idx & 511;
    float v = W2[(size_t)k * DM + n];
    g_wh[idx] = __float2half(v);
}

// ---------------- GEMM1 fused: hid = gelu(feat @ W1 + b1) -> fp16 ---------
__global__ void gemm1_fused_kernel(const float* __restrict__ W1,
                                   const float* __restrict__ b1)
{
    __shared__ float W1s[15 * DM];
    __shared__ float b1s[DM];
    int tid = threadIdx.x;                 // 256
    for (int i = tid; i < 15 * DM; i += 256) W1s[i] = W1[i];
    for (int i = tid; i < DM; i += 256)      b1s[i] = b1[i];
    __syncthreads();

    int warp = tid >> 5, lane = tid & 31;
    int row0 = (blockIdx.x * 8 + warp) * 32;

    for (int rr = 0; rr < 32; rr++) {
        int row = row0 + rr;
        const float* fr = g_feat + (size_t)row * 15;
        float a[15];
        #pragma unroll
        for (int k = 0; k < 15; k++) a[k] = fr[k];
        #pragma unroll 4
        for (int i = 0; i < 16; i++) {
            int n = lane + i * 32;
            float acc = b1s[n];
            #pragma unroll
            for (int k = 0; k < 15; k++)
                acc = fmaf(a[k], W1s[k * DM + n], acc);
            float gv = gelu_exact(acc);
            g_hh[(size_t)row * DM + n] = __float2half(gv);
        }
    }
}

// ---------------- LayerNorm over DM from fp16 z, write fp32 tokens ---------
__global__ void ln_kernel(const float* __restrict__ gam,
                          const float* __restrict__ bet,
                          float* __restrict__ out)
{
    int row = blockIdx.x;
    int tid = threadIdx.x;               // 128 threads
    const __half2* in2 = (const __half2*)(g_tokh + (size_t)row * DM);
    // each thread handles 2 half2 = 4 values
    float2 v0 = __half22float2(in2[tid * 2]);
    float2 v1 = __half22float2(in2[tid * 2 + 1]);
    float s  = v0.x + v0.y + v1.x + v1.y;
    float ss = v0.x*v0.x + v0.y*v0.y + v1.x*v1.x + v1.y*v1.y;

    __shared__ float shs[4], shss[4];
    #pragma unroll
    for (int off = 16; off; off >>= 1) {
        s  += __shfl_down_sync(0xffffffffu, s,  off);
        ss += __shfl_down_sync(0xffffffffu, ss, off);
    }
    int wid = tid >> 5, lane = tid & 31;
    if (lane == 0) { shs[wid] = s; shss[wid] = ss; }
    __syncthreads();
    float tsum  = shs[0] + shs[1] + shs[2] + shs[3];
    float tsum2 = shss[0] + shss[1] + shss[2] + shss[3];
    float mu  = tsum * (1.f / DM);
    float var = tsum2 * (1.f / DM) - mu * mu;
    float rs  = rsqrtf(var + LN_EPS);

    float4 gv = ((const float4*)gam)[tid];
    float4 bv = ((const float4*)bet)[tid];
    float4 o;
    o.x = (v0.x - mu) * rs * gv.x + bv.x;
    o.y = (v0.y - mu) * rs * gv.y + bv.y;
    o.z = (v1.x - mu) * rs * gv.z + bv.z;
    o.w = (v1.y - mu) * rs * gv.w + bv.w;
    ((float4*)(out + (size_t)row * DM))[tid] = o;
}

// ---------------- launch ----------------
static void* symaddr(const void* s) {
    void* p = nullptr;
    cudaGetSymbolAddress(&p, s);
    return p;
}

extern "C" void kernel_launch(void* const* d_in, const int* in_sizes, int n_in,
                              void* d_out, int out_size)
{
    const float* x    = (const float*)d_in[0];
    const float* spos = (const float*)d_in[1];
    const void*  smask = (const void*)d_in[2];
    const float* Wf1 = (const float*)d_in[3];
    const float* bf1 = (const float*)d_in[4];
    const float* Wf2 = (const float*)d_in[5];
    const float* bf2 = (const float*)d_in[6];
    const float* lng = (const float*)d_in[7];
    const float* lnb = (const float*)d_in[8];
    const float* Wd1 = (const float*)d_in[9];
    const float* bd1 = (const float*)d_in[10];
    const float* Wd2 = (const float*)d_in[11];
    const float* bd2 = (const float*)d_in[12];
    float* out = (float*)d_out;

    __nv_bfloat16* xh = (__nv_bfloat16*)symaddr(g_xh);
    __nv_bfloat16* xl = (__nv_bfloat16*)symaddr(g_xl);
    __nv_bfloat16* bh = (__nv_bfloat16*)symaddr(g_bh);
    __nv_bfloat16* bl = (__nv_bfloat16*)symaddr(g_bl);
    __half* hh = (__half*)symaddr(g_hh);
    __half* wh = (__half*)symaddr(g_wh);
    __half* tokh = (__half*)symaddr(g_tokh);
    float* zbias = (float*)symaddr(g_zbias);
    float* H     = (float*)symaddr(g_H);
    float* desc  = (float*)symaddr(g_desc);
    float* hd    = (float*)symaddr(g_hd);

    static int attr_set = 0;
    if (!attr_set) {
        cudaFuncSetAttribute(mma3_kernel,
                             cudaFuncAttributeMaxDynamicSharedMemorySize,
                             MM_SMEM);
        cudaFuncSetAttribute(mma1h_kernel,
                             cudaFuncAttributeMaxDynamicSharedMemorySize,
                             MM2_SMEM);
        attr_set = 1;
    }

    // 0) mask dtype detect + convert
    mask_convert_kernel<<<1, 256>>>(smask);
    // 1) basis (transposed, split)
    init_basis_kernel<<<(HCOLS*KPAD + 255)/256, 256>>>();
    // 2) x split to bf16 hi/lo + per-block energy (single pass over x)
    xsplit_energy_kernel<<<NROWS_A/8, 256>>>(x);
    // 3) half-block DFT on tensor cores (bf16 3-pass): -> g_H
    mma3_kernel<<<dim3(1, NROWS_A/128), 256, MM_SMEM>>>(
        xh, xl, bh, bl, H, zbias, KPAD, KPAD, HCOLS, KPAD/32);
    // 4) spectral features per token
    stageB_kernel<<<NTOK/8, 256>>>(spos);
    // 5) channel reductions + desc + topo_dev
    stageC_kernel<<<NBW, 64>>>(spos);
    // 6) W2 transpose -> fp16 (tiny)
    w2split_kernel<<<(DM*DM)/256, 256>>>(Wf2);
    // 7) token MLP layer 1 fused: gelu(feat W1 + b1) -> fp16
    gemm1_fused_kernel<<<NTOK/256, 256>>>(Wf1, bf1);
    // 8) token MLP layer 2 on tensor cores (fp16, fp16 out) -> g_tokh
    mma1h_kernel<<<dim3(DM/128, NTOK/128), 256, MM2_SMEM>>>(
        hh, wh, tokh, bf2, DM, DM, DM, DM/32);
    // 9) LayerNorm from fp16 z -> tokens output
    ln_kernel<<<NTOK, 128>>>(lng, lnb, out);
    // 10) desc MLP layer 1
    sgemm_bias_act<<<dim3(DM/128, (NBW + 127)/128), 256>>>(desc, Wd1, bd1, hd,
                                                           NBW, DM, 11, 1);
    // 11) desc MLP layer 2 -> desc output
    sgemm_bias_act<<<dim3(DM/128, (NBW + 127)/128), 256>>>(hd, Wd2, bd2,
                                                           out + TOK_ELEMS,
                                                           NBW, DM, DM, 0);
    (void)in_sizes; (void)n_in; (void)out_size;
}

// round 17
// speedup vs baseline: 1.3819x; 1.2706x over previous
#include <cuda_runtime.h>
#include <cuda_bf16.h>
#include <cuda_fp16.h>
#include <math.h>
#include <stdint.h>

// ---------------- problem constants ----------------
#define BB   16
#define NCH  64
#define TT   15000
#define WS   500
#define STp  250
#define NW   59              // (T-WS)/ST + 1
#define NBLK 60              // half-blocks per channel
#define NBINS 58             // k = 2..59
#define DM   512
#define EPSc 1e-6f
#define LN_EPS 1e-5f

#define NROWS_A   (BB*NCH*NBLK)      // 61440  half-block rows
#define NTOK      (BB*NW*NCH)        // 60416
#define NBW       (BB*NW)            // 944
#define HCOLS     128                // padded H width
#define KPAD      256                // padded DFT K (250 -> 256)
#define TOK_ELEMS (NTOK*DM)

#ifndef M_PI
#define M_PI 3.14159265358979323846
#endif

// ---------------- scratch (static device globals) ----------------
__device__ float g_zbias[DM];
__device__ float g_H[(size_t)NROWS_A*HCOLS];
__device__ float g_E[NROWS_A];
__device__ float g_feat[(size_t)NTOK*15];
__device__ float g_bp[(size_t)NTOK*4];
__device__ float g_desc[(size_t)NBW*11];
__device__ float g_hd[(size_t)NBW*DM];
__device__ float g_maskf[BB*NCH];
__device__ float g_tok[(size_t)NTOK*DM];
// bf16 split operands (DFT, 3-pass)
__device__ __nv_bfloat16 g_xh[(size_t)NROWS_A*KPAD];   // x half-blocks hi
__device__ __nv_bfloat16 g_xl[(size_t)NROWS_A*KPAD];   // x half-blocks lo
__device__ __nv_bfloat16 g_bh[HCOLS*KPAD];             // DFT basis^T hi [t][k]
__device__ __nv_bfloat16 g_bl[HCOLS*KPAD];             // DFT basis^T lo
// fp16 operands (token GEMM2, single pass)
__device__ __half g_hh[(size_t)NTOK*DM];               // fp16(gelu(feat W1 + b1))
__device__ __half g_wh[DM*DM];                         // Wf2^T fp16 [n][k]

// ================= portable PTX helpers (sm_80+ baseline) ==================
__device__ __forceinline__ uint32_t smem_u32(const void* p) {
    uint32_t a;
    asm("{ .reg .u64 t; cvta.to.shared.u64 t, %1; cvt.u32.u64 %0, t; }"
        : "=r"(a) : "l"(p));
    return a;
}

// Swizzle for 64-byte-wide rows (Swizzle<2,4,3>)
#define SWZ64(off)  ((off) ^ (((off) >> 3) & 0x30))

#define CP_ASYNC16(dst, src) \
    asm volatile("cp.async.cg.shared.global [%0], [%1], 16;" :: "r"(dst), "l"(src))
#define CP_COMMIT() asm volatile("cp.async.commit_group;" ::: "memory")
#define CP_WAIT0()  asm volatile("cp.async.wait_group 0;" ::: "memory")
#define CP_WAIT1()  asm volatile("cp.async.wait_group 1;" ::: "memory")

__device__ __forceinline__ void ldsm_x4(uint32_t& r0, uint32_t& r1,
                                        uint32_t& r2, uint32_t& r3, uint32_t addr) {
    asm volatile("ldmatrix.sync.aligned.m8n8.x4.shared.b16 {%0,%1,%2,%3}, [%4];"
                 : "=r"(r0), "=r"(r1), "=r"(r2), "=r"(r3) : "r"(addr));
}
__device__ __forceinline__ void ldsm_x2(uint32_t& r0, uint32_t& r1, uint32_t addr) {
    asm volatile("ldmatrix.sync.aligned.m8n8.x2.shared.b16 {%0,%1}, [%2];"
                 : "=r"(r0), "=r"(r1) : "r"(addr));
}
__device__ __forceinline__ void mma_bf16(float* c, const uint32_t* a, const uint32_t* b) {
    asm volatile(
        "mma.sync.aligned.m16n8k16.row.col.f32.bf16.bf16.f32 "
        "{%0,%1,%2,%3}, {%4,%5,%6,%7}, {%8,%9}, {%0,%1,%2,%3};"
        : "+f"(c[0]), "+f"(c[1]), "+f"(c[2]), "+f"(c[3])
        : "r"(a[0]), "r"(a[1]), "r"(a[2]), "r"(a[3]), "r"(b[0]), "r"(b[1]));
}
__device__ __forceinline__ void mma_f16(float* c, const uint32_t* a, const uint32_t* b) {
    asm volatile(
        "mma.sync.aligned.m16n8k16.row.col.f32.f16.f16.f32 "
        "{%0,%1,%2,%3}, {%4,%5,%6,%7}, {%8,%9}, {%0,%1,%2,%3};"
        : "+f"(c[0]), "+f"(c[1]), "+f"(c[2]), "+f"(c[3])
        : "r"(a[0]), "r"(a[1]), "r"(a[2]), "r"(a[3]), "r"(b[0]), "r"(b[1]));
}

// ---------------- mask dtype detection + conversion ----------------
__global__ void mask_convert_kernel(const void* mptr) {
    __shared__ int s_anyFloat, s_anyHighByte, s_mode;
    int tid = threadIdx.x;
    if (tid == 0) { s_anyFloat = 0; s_anyHighByte = 0; }
    __syncthreads();
    unsigned int w = ((const unsigned int*)mptr)[tid];
    if (w == 0x3F800000u) atomicOr(&s_anyFloat, 1);
    else if ((w & 0xFFFFFF00u) != 0u) atomicOr(&s_anyHighByte, 1);
    __syncthreads();
    if (tid == 0)
        s_mode = s_anyFloat ? 2 : (s_anyHighByte ? 0 : 1);
    __syncthreads();
    int mode = s_mode;
    for (int i = tid; i < BB*NCH; i += 256) {
        float m;
        if (mode == 2)      m = (((const float*)mptr)[i] != 0.f) ? 1.f : 0.f;
        else if (mode == 1) m = (((const int*)mptr)[i]   != 0)   ? 1.f : 0.f;
        else                m = (((const unsigned char*)mptr)[i] != 0) ? 1.f : 0.f;
        g_maskf[i] = m;
    }
}

// ---------------- basis init: B^T [t][k], bf16 hi/lo split ----------------
__global__ void init_basis_kernel() {
    int idx = blockIdx.x * blockDim.x + threadIdx.x;   // 128*256
    if (idx < DM) g_zbias[idx] = 0.f;
    if (idx >= HCOLS*KPAD) return;
    int t = idx >> 8;          // column 0..127
    int n = idx & 255;         // sample 0..255
    float v = 0.f;
    if (n < 250) {
        if (t < NBINS) {
            int k = t + 2;
            int ph = (k * n) % 500;
            v = (float)cos((2.0 * M_PI / 500.0) * (double)ph);
        } else if (t < 2*NBINS) {
            int k = (t - NBINS) + 2;
            int ph = (k * n) % 500;
            v = (float)(-sin((2.0 * M_PI / 500.0) * (double)ph));
        } else if (t == 116) {
            v = 1.f;
        } else if (t == 117) {
            v = (n & 1) ? -1.f : 1.f;
        }
    }
    __nv_bfloat16 hi = __float2bfloat16(v);
    g_bh[idx] = hi;
    g_bl[idx] = __float2bfloat16(v - __bfloat162float(hi));
}

// ---------------- x split to bf16 hi/lo + per-block energy ----------------
__global__ void xsplit_energy_kernel(const float* __restrict__ x) {
    int gw   = (blockIdx.x * blockDim.x + threadIdx.x) >> 5;
    int lane = threadIdx.x & 31;
    if (gw >= NROWS_A) return;
    const float* p = x + (size_t)gw * 250;
    __nv_bfloat16* ph = g_xh + (size_t)gw * KPAD;
    __nv_bfloat16* pl = g_xl + (size_t)gw * KPAD;
    float s = 0.f;
    #pragma unroll
    for (int j = 0; j < 8; j++) {
        int i = lane + j * 32;
        float v = (i < 250) ? p[i] : 0.f;
        s = fmaf(v, v, s);
        __nv_bfloat16 hi = __float2bfloat16(v);
        ph[i] = hi;
        pl[i] = __float2bfloat16(v - __bfloat162float(hi));
    }
    #pragma unroll
    for (int off = 16; off; off >>= 1) s += __shfl_down_sync(0xffffffffu, s, off);
    if (lane == 0) g_E[gw] = s;
}

// ---------------- bf16 3-pass split MMA GEMM (DFT) ------------------------
// CTA tile 128x128, BK=32, 256 threads = 8 warps (2m x 4n), warp tile 64x32.
#define MM_BUF   32768
#define MM_SMEM  (2*MM_BUF + 1024)

__global__ void __launch_bounds__(256, 2)
mma3_kernel(const __nv_bfloat16* __restrict__ Ah,
            const __nv_bfloat16* __restrict__ Al,
            const __nv_bfloat16* __restrict__ Bh,
            const __nv_bfloat16* __restrict__ Bl,
            float* __restrict__ C,
            const float* __restrict__ bias,
            int ldA, int ldB, int ldC, int ktiles)   // ktiles = K/32
{
    extern __shared__ char sm[];
    uint32_t su = smem_u32(sm);
    float* biasS = (float*)(sm + 2*MM_BUF);

    int tid  = threadIdx.x;
    int wid  = tid >> 5;
    int lane = tid & 31;
    int m0   = blockIdx.y * 128;
    int n0   = blockIdx.x * 128;

    for (int i = tid; i < 128; i += 256) biasS[i] = bias[n0 + i];

    int wm = wid & 1;
    int wn = wid >> 1;

    float acc[4][4][4];
    #pragma unroll
    for (int mi = 0; mi < 4; mi++)
        #pragma unroll
        for (int ni = 0; ni < 4; ni++)
            #pragma unroll
            for (int q = 0; q < 4; q++) acc[mi][ni][q] = 0.f;

    int aRow = lane & 15;
    int aKb  = (lane >> 4) << 4;
    int bRow = lane & 7;
    int bKb  = ((lane >> 3) & 1) << 4;

    auto load_stage = [&](int kt, int buf) {
        int k0 = kt * 32;
        uint32_t base = su + (uint32_t)buf * MM_BUF;
        #pragma unroll
        for (int i = 0; i < 8; i++) {
            int ci  = tid + i * 256;
            int mat = ci >> 9;
            int rem = ci & 511;
            int row = rem >> 2;
            int col = rem & 3;
            uint32_t dst = base + (uint32_t)(mat << 13)
                         + SWZ64((uint32_t)(row * 64 + col * 16));
            const __nv_bfloat16* src;
            if      (mat == 0) src = Ah + (size_t)(m0 + row) * ldA + k0 + col * 8;
            else if (mat == 1) src = Al + (size_t)(m0 + row) * ldA + k0 + col * 8;
            else if (mat == 2) src = Bh + (size_t)(n0 + row) * ldB + k0 + col * 8;
            else               src = Bl + (size_t)(n0 + row) * ldB + k0 + col * 8;
            CP_ASYNC16(dst, src);
        }
        CP_COMMIT();
    };

    load_stage(0, 0);

    for (int kt = 0; kt < ktiles; kt++) {
        if (kt + 1 < ktiles) {
            load_stage(kt + 1, (kt + 1) & 1);
            CP_WAIT1();
        } else {
            CP_WAIT0();
        }
        __syncthreads();

        uint32_t base = su + (uint32_t)(kt & 1) * MM_BUF;
        uint32_t aHT = base;
        uint32_t aLT = base + 8192u;
        uint32_t bHT = base + 16384u;
        uint32_t bLT = base + 24576u;

        #pragma unroll
        for (int k16 = 0; k16 < 2; k16++) {
            uint32_t bh[4][2], bl[4][2];
            #pragma unroll
            for (int ni = 0; ni < 4; ni++) {
                uint32_t off = (uint32_t)((wn * 32 + ni * 8 + bRow) * 64
                                          + k16 * 32 + bKb);
                ldsm_x2(bh[ni][0], bh[ni][1], bHT + SWZ64(off));
                ldsm_x2(bl[ni][0], bl[ni][1], bLT + SWZ64(off));
            }
            uint32_t a[4][4];
            #pragma unroll
            for (int mi = 0; mi < 4; mi++) {
                uint32_t off = (uint32_t)((wm * 64 + mi * 16 + aRow) * 64
                                          + k16 * 32 + aKb);
                ldsm_x4(a[mi][0], a[mi][1], a[mi][2], a[mi][3], aHT + SWZ64(off));
            }
            #pragma unroll
            for (int mi = 0; mi < 4; mi++)
                #pragma unroll
                for (int ni = 0; ni < 4; ni++)
                    mma_bf16(acc[mi][ni], a[mi], bh[ni]);
            #pragma unroll
            for (int mi = 0; mi < 4; mi++)
                #pragma unroll
                for (int ni = 0; ni < 4; ni++)
                    mma_bf16(acc[mi][ni], a[mi], bl[ni]);
            #pragma unroll
            for (int mi = 0; mi < 4; mi++) {
                uint32_t off = (uint32_t)((wm * 64 + mi * 16 + aRow) * 64
                                          + k16 * 32 + aKb);
                ldsm_x4(a[mi][0], a[mi][1], a[mi][2], a[mi][3], aLT + SWZ64(off));
            }
            #pragma unroll
            for (int mi = 0; mi < 4; mi++)
                #pragma unroll
                for (int ni = 0; ni < 4; ni++)
                    mma_bf16(acc[mi][ni], a[mi], bh[ni]);
        }
        __syncthreads();
    }

    int rql = lane >> 2;
    int cql = (lane & 3) * 2;
    #pragma unroll
    for (int mi = 0; mi < 4; mi++) {
        #pragma unroll
        for (int ni = 0; ni < 4; ni++) {
            int r0 = m0 + wm * 64 + mi * 16 + rql;
            int c0 = n0 + wn * 32 + ni * 8 + cql;
            int cl = wn * 32 + ni * 8 + cql;
            float2 v0 = make_float2(acc[mi][ni][0] + biasS[cl],
                                    acc[mi][ni][1] + biasS[cl + 1]);
            float2 v1 = make_float2(acc[mi][ni][2] + biasS[cl],
                                    acc[mi][ni][3] + biasS[cl + 1]);
            *((float2*)(C + (size_t)r0 * ldC + c0)) = v0;
            *((float2*)(C + (size_t)(r0 + 8) * ldC + c0)) = v1;
        }
    }
}

// ---------------- fp16 single-pass MMA GEMM (token GEMM2) ------------------
// C = A * B^T + bias (fp32 out).  CTA tile 128x128, BK=32, 256 thr,
// 8 warps (2m x 4n), warp tile 64x32. Stage: a @0 (8KB), b @8192 -> 16KB.
#define MM2_BUF   16384
#define MM2_SMEM  (2*MM2_BUF + 1024)

__global__ void __launch_bounds__(256, 2)
mma1h_kernel(const __half* __restrict__ A,
             const __half* __restrict__ B,
             float* __restrict__ C,
             const float* __restrict__ bias,
             int ldA, int ldB, int ldC, int ktiles)   // ktiles = K/32
{
    extern __shared__ char sm[];
    uint32_t su = smem_u32(sm);
    float* biasS = (float*)(sm + 2*MM2_BUF);

    int tid  = threadIdx.x;
    int wid  = tid >> 5;
    int lane = tid & 31;
    int m0   = blockIdx.y * 128;
    int n0   = blockIdx.x * 128;

    for (int i = tid; i < 128; i += 256) biasS[i] = bias[n0 + i];

    int wm = wid & 1;
    int wn = wid >> 1;

    float acc[4][4][4];
    #pragma unroll
    for (int mi = 0; mi < 4; mi++)
        #pragma unroll
        for (int ni = 0; ni < 4; ni++)
            #pragma unroll
            for (int q = 0; q < 4; q++) acc[mi][ni][q] = 0.f;

    int aRow = lane & 15;
    int aKb  = (lane >> 4) << 4;
    int bRow = lane & 7;
    int bKb  = ((lane >> 3) & 1) << 4;

    auto load_stage = [&](int kt, int buf) {
        int k0 = kt * 32;
        uint32_t base = su + (uint32_t)buf * MM2_BUF;
        #pragma unroll
        for (int i = 0; i < 4; i++) {
            int ci  = tid + i * 256;
            int mat = ci >> 9;              // 0=a 1=b
            int rem = ci & 511;
            int row = rem >> 2;
            int col = rem & 3;
            uint32_t dst = base + (uint32_t)(mat << 13)
                         + SWZ64((uint32_t)(row * 64 + col * 16));
            const __half* src;
            if (mat == 0) src = A + (size_t)(m0 + row) * ldA + k0 + col * 8;
            else          src = B + (size_t)(n0 + row) * ldB + k0 + col * 8;
            CP_ASYNC16(dst, src);
        }
        CP_COMMIT();
    };

    load_stage(0, 0);

    for (int kt = 0; kt < ktiles; kt++) {
        if (kt + 1 < ktiles) {
            load_stage(kt + 1, (kt + 1) & 1);
            CP_WAIT1();
        } else {
            CP_WAIT0();
        }
        __syncthreads();

        uint32_t base = su + (uint32_t)(kt & 1) * MM2_BUF;
        uint32_t aT = base;
        uint32_t bT = base + 8192u;

        #pragma unroll
        for (int k16 = 0; k16 < 2; k16++) {
            uint32_t b[4][2];
            #pragma unroll
            for (int ni = 0; ni < 4; ni++) {
                uint32_t off = (uint32_t)((wn * 32 + ni * 8 + bRow) * 64
                                          + k16 * 32 + bKb);
                ldsm_x2(b[ni][0], b[ni][1], bT + SWZ64(off));
            }
            uint32_t a[4][4];
            #pragma unroll
            for (int mi = 0; mi < 4; mi++) {
                uint32_t off = (uint32_t)((wm * 64 + mi * 16 + aRow) * 64
                                          + k16 * 32 + aKb);
                ldsm_x4(a[mi][0], a[mi][1], a[mi][2], a[mi][3], aT + SWZ64(off));
            }
            #pragma unroll
            for (int mi = 0; mi < 4; mi++)
                #pragma unroll
                for (int ni = 0; ni < 4; ni++)
                    mma_f16(acc[mi][ni], a[mi], b[ni]);
        }
        __syncthreads();
    }

    int rql = lane >> 2;
    int cql = (lane & 3) * 2;
    #pragma unroll
    for (int mi = 0; mi < 4; mi++) {
        #pragma unroll
        for (int ni = 0; ni < 4; ni++) {
            int r0 = m0 + wm * 64 + mi * 16 + rql;
            int c0 = n0 + wn * 32 + ni * 8 + cql;
            int cl = wn * 32 + ni * 8 + cql;
            float2 v0 = make_float2(acc[mi][ni][0] + biasS[cl],
                                    acc[mi][ni][1] + biasS[cl + 1]);
            float2 v1 = make_float2(acc[mi][ni][2] + biasS[cl],
                                    acc[mi][ni][3] + biasS[cl + 1]);
            *((float2*)(C + (size_t)r0 * ldC + c0)) = v0;
            *((float2*)(C + (size_t)(r0 + 8) * ldC + c0)) = v1;
        }
    }
}

// ---------------- generic fp32 SGEMM (desc MLPs only) ----------------
__device__ __forceinline__ float gelu_exact(float x) {
    return 0.5f * x * (1.f + erff(x * 0.70710678118654752f));
}

__global__ void sgemm_bias_act(const float* __restrict__ A,
                               const float* __restrict__ Bm,
                               const float* __restrict__ bias,
                               float* __restrict__ C,
                               int M, int N, int K, int act)
{
    const int BMt = 128, BNt = 128, BKt = 16;
    __shared__ __align__(16) float As[BKt][BMt];
    __shared__ __align__(16) float Bs[BKt][BNt];

    int tid = threadIdx.x;
    int m0 = blockIdx.y * BMt;
    int n0 = blockIdx.x * BNt;
    int ty = tid >> 4;
    int tx = tid & 15;

    float acc[8][8];
    #pragma unroll
    for (int i = 0; i < 8; i++)
        #pragma unroll
        for (int j = 0; j < 8; j++) acc[i][j] = 0.f;

    for (int k0 = 0; k0 < K; k0 += BKt) {
        #pragma unroll
        for (int i = 0; i < 8; i++) {
            int idx = tid + i * 256;
            int ar = idx >> 4;
            int ac = idx & 15;
            int gm = m0 + ar, gk = k0 + ac;
            float v = 0.f;
            if (gm < M && gk < K) v = A[(size_t)gm * K + gk];
            As[ac][ar] = v;
        }
        #pragma unroll
        for (int i = 0; i < 8; i++) {
            int idx = tid + i * 256;
            int br = idx >> 7;
            int bc = idx & 127;
            int gk = k0 + br, gn = n0 + bc;
            float v = 0.f;
            if (gk < K && gn < N) v = Bm[(size_t)gk * N + gn];
            Bs[br][bc] = v;
        }
        __syncthreads();
        #pragma unroll
        for (int kk = 0; kk < BKt; kk++) {
            float4 a0 = ((const float4*)As[kk])[ty * 2];
            float4 a1 = ((const float4*)As[kk])[ty * 2 + 1];
            float4 b0 = ((const float4*)Bs[kk])[tx * 2];
            float4 b1 = ((const float4*)Bs[kk])[tx * 2 + 1];
            float a[8] = {a0.x,a0.y,a0.z,a0.w,a1.x,a1.y,a1.z,a1.w};
            float b[8] = {b0.x,b0.y,b0.z,b0.w,b1.x,b1.y,b1.z,b1.w};
            #pragma unroll
            for (int i = 0; i < 8; i++)
                #pragma unroll
                for (int j = 0; j < 8; j++)
                    acc[i][j] = fmaf(a[i], b[j], acc[i][j]);
        }
        __syncthreads();
    }

    #pragma unroll
    for (int i = 0; i < 8; i++) {
        int gm = m0 + ty * 8 + i;
        if (gm >= M) continue;
        #pragma unroll
        for (int j = 0; j < 8; j++) {
            int gn = n0 + tx * 8 + j;
            if (gn >= N) continue;
            float v = acc[i][j] + bias[gn];
            if (act) v = gelu_exact(v);
            C[(size_t)gm * N + gn] = v;
        }
    }
}

// ---------------- stage B: spectral features per (b,w,c) -------------------
__global__ void stageB_kernel(const float* __restrict__ sensor_pos)
{
    int gw   = (blockIdx.x * blockDim.x + threadIdx.x) >> 5;
    int lane = threadIdx.x & 31;
    if (gw >= NTOK) return;

    int b   = gw / (NW * NCH);
    int rem = gw % (NW * NCH);
    int w   = rem / NCH;
    int c   = rem % NCH;
    int bcn = b * NCH + c;

    const float* H1 = g_H + ((size_t)(bcn * NBLK + w)) * HCOLS;
    const float* H2 = H1 + HCOLS;

    float s0 = 0.f, s1 = 0.f, s2 = 0.f, s3 = 0.f;
    float sa = 0.f, saf = 0.f, pmax = 0.f;
    float sg = (lane & 1) ? -1.f : 1.f;

    #pragma unroll
    for (int rep = 0; rep < 2; rep++) {
        int t = lane + rep * 32;
        if (t < NBINS) {
            float cr1 = H1[t],         ci1 = H1[NBINS + t];
            float cr2 = H2[t],         ci2 = H2[NBINS + t];
            float xr = cr1 + sg * cr2;
            float xi = ci1 + sg * ci2;
            float p  = xr * xr + xi * xi;
            int k = t + 2;
            if      (k <= 7)  s0 += p;
            else if (k <= 15) s1 += p;
            else if (k <= 25) s2 += p;
            else              s3 += p;
            if (k >= 14 && k <= 27) {
                sa  += p;
                saf += p * (0.5f * (float)k);
                pmax = fmaxf(pmax, p);
            }
        }
    }
    #pragma unroll
    for (int off = 16; off; off >>= 1) {
        s0  += __shfl_down_sync(0xffffffffu, s0,  off);
        s1  += __shfl_down_sync(0xffffffffu, s1,  off);
        s2  += __shfl_down_sync(0xffffffffu, s2,  off);
        s3  += __shfl_down_sync(0xffffffffu, s3,  off);
        sa  += __shfl_down_sync(0xffffffffu, sa,  off);
        saf += __shfl_down_sync(0xffffffffu, saf, off);
        pmax = fmaxf(pmax, __shfl_down_sync(0xffffffffu, pmax, off));
    }

    if (lane == 0) {
        float m = g_maskf[bcn];
        float su  = H1[116] + H2[116];
        float alt = H1[117] + H2[117];
        int   rA  = bcn * NBLK + w;
        float e   = g_E[rA] + g_E[rA + 1];
        float Ec  = fmaxf(e - su * su * (1.f / 500.f), 0.f);
        float sumsq = 0.5f * (500.f * Ec + alt * alt);
        float pm  = m * sumsq * (1.f / 251.f) + EPSc;

        float bp0 = m * s0 * (1.f / 6.f)  + EPSc;
        float bp1 = m * s1 * (1.f / 8.f)  + EPSc;
        float bp2 = m * s2 * (1.f / 10.f) + EPSc;
        float bp3 = m * s3 * (1.f / 34.f) + EPSc;
        float total = fmaxf(bp0 + bp1 + bp2 + bp3, EPSc);

        float asum = fmaxf(m * sa + 14.f * EPSc, EPSc);
        float af   = m * saf + 143.5f * EPSc;
        float pkf  = af / asum;
        float amax = m * pmax + EPSc;
        float score = amax / fmaxf(pm, EPSc);
        float py = sensor_pos[bcn * 2 + 1];

        float* f = g_feat + (size_t)gw * 15;
        f[0] = logf(bp0); f[1] = logf(bp1); f[2] = logf(bp2); f[3] = logf(bp3);
        f[4] = bp0 / total; f[5] = bp1 / total; f[6] = bp2 / total; f[7] = bp3 / total;
        f[12] = pkf; f[13] = score; f[14] = py;
        *((float4*)(g_bp + (size_t)gw * 4)) = make_float4(bp0, bp1, bp2, bp3);
    }
}

// ---------------- stage C: channel reductions, desc, topo_dev --------------
__global__ void stageC_kernel(const float* __restrict__ sensor_pos)
{
    __shared__ float red[17][65];
    __shared__ float blog[4];
    int bw = blockIdx.x;
    int b  = bw / NW;
    int c  = threadIdx.x;
    int g  = bw * NCH + c;
    int bcn = b * NCH + c;

    float4 bp4 = *((const float4*)(g_bp + (size_t)g * 4));
    float bp[4] = {bp4.x, bp4.y, bp4.z, bp4.w};
    float m  = g_maskf[bcn];
    float px = sensor_pos[bcn * 2 + 0];
    float py = sensor_pos[bcn * 2 + 1];
    float total = fmaxf(bp[0] + bp[1] + bp[2] + bp[3], EPSc);
    float alpha = bp[2];

    float L = (px < -0.02f && m > 0.f) ? 1.f : 0.f;
    float R = (px >  0.02f && m > 0.f) ? 1.f : 0.f;
    float P = (py < -0.02f && m > 0.f) ? 1.f : 0.f;
    float A = (py >  0.02f && m > 0.f) ? 1.f : 0.f;

    red[0][c] = m;
    red[1][c] = m * bp[0];  red[2][c] = m * bp[1];
    red[3][c] = m * bp[2];  red[4][c] = m * bp[3];
    red[5][c] = m * bp[0] / total;  red[6][c] = m * bp[1] / total;
    red[7][c] = m * bp[2] / total;  red[8][c] = m * bp[3] / total;
    red[9][c]  = alpha * L;  red[10][c] = L;
    red[11][c] = alpha * R;  red[12][c] = R;
    red[13][c] = alpha * P;  red[14][c] = P;
    red[15][c] = alpha * A;  red[16][c] = A;
    __syncthreads();

    for (int off = 32; off >= 1; off >>= 1) {
        if (c < off) {
            #pragma unroll
            for (int q = 0; q < 17; q++) red[q][c] += red[q][c + off];
        }
        __syncthreads();
    }

    if (c == 0) {
        float cnt = fmaxf(red[0][0], 1.f);
        float cm[4], brm[4];
        #pragma unroll
        for (int i = 0; i < 4; i++) {
            cm[i]  = red[1 + i][0] / cnt;
            brm[i] = red[5 + i][0] / cnt;
        }
        float Lm = red[9][0]  / fmaxf(red[10][0], 1.f);
        float Rm = red[11][0] / fmaxf(red[12][0], 1.f);
        float Pm = red[13][0] / fmaxf(red[14][0], 1.f);
        float Am = red[15][0] / fmaxf(red[16][0], 1.f);
        float asym = (Lm - Rm) / fmaxf(Lm + Rm + EPSc, EPSc);
        float ap   = (Pm - Am) / fmaxf(Pm + Am + EPSc, EPSc);
        bool support = (red[16][0] > 0.f) && (red[14][0] > 0.f);
        if (!support) ap = 0.f;

        float* d = g_desc + (size_t)bw * 11;
        #pragma unroll
        for (int i = 0; i < 4; i++) {
            float bl = logf(fmaxf(cm[i], EPSc));
            d[i] = bl;
            d[4 + i] = brm[i];
            blog[i] = bl;
        }
        d[8] = asym; d[9] = ap; d[10] = brm[0] + brm[1];
    }
    __syncthreads();

    float* f = g_feat + (size_t)g * 15;
    #pragma unroll
    for (int i = 0; i < 4; i++)
        f[8 + i] = logf(bp[i]) - blog[i];
}

// ---------------- W2 transpose -> fp16 ----------------
__global__ void w2split_kernel(const float* __restrict__ W2) {
    int idx = blockIdx.x * blockDim.x + threadIdx.x;   // 512*512
    int n = idx >> 9;
    int k = idx & 511;
    float v = W2[(size_t)k * DM + n];
    g_wh[idx] = __float2half(v);
}

// ---------------- GEMM1 fused: hid = gelu(feat @ W1 + b1) -> fp16 ---------
__global__ void gemm1_fused_kernel(const float* __restrict__ W1,
                                   const float* __restrict__ b1)
{
    __shared__ float W1s[15 * DM];
    __shared__ float b1s[DM];
    int tid = threadIdx.x;                 // 256
    for (int i = tid; i < 15 * DM; i += 256) W1s[i] = W1[i];
    for (int i = tid; i < DM; i += 256)      b1s[i] = b1[i];
    __syncthreads();

    int warp = tid >> 5, lane = tid & 31;
    int row0 = (blockIdx.x * 8 + warp) * 32;

    for (int rr = 0; rr < 32; rr++) {
        int row = row0 + rr;
        const float* fr = g_feat + (size_t)row * 15;
        float a[15];
        #pragma unroll
        for (int k = 0; k < 15; k++) a[k] = fr[k];
        #pragma unroll 4
        for (int i = 0; i < 16; i++) {
            int n = lane + i * 32;
            float acc = b1s[n];
            #pragma unroll
            for (int k = 0; k < 15; k++)
                acc = fmaf(a[k], W1s[k * DM + n], acc);
            float gv = gelu_exact(acc);
            g_hh[(size_t)row * DM + n] = __float2half(gv);
        }
    }
}

// ---------------- LayerNorm over DM, write tokens to output ----------------
__global__ void ln_kernel(const float* __restrict__ gam,
                          const float* __restrict__ bet,
                          float* __restrict__ out)
{
    int row = blockIdx.x;
    int tid = threadIdx.x;               // 128 threads x float4
    const float4* in4 = (const float4*)(g_tok + (size_t)row * DM);
    float4 v = in4[tid];
    float s  = v.x + v.y + v.z + v.w;
    float ss = v.x*v.x + v.y*v.y + v.z*v.z + v.w*v.w;

    __shared__ float shs[4], shss[4];
    #pragma unroll
    for (int off = 16; off; off >>= 1) {
        s  += __shfl_down_sync(0xffffffffu, s,  off);
        ss += __shfl_down_sync(0xffffffffu, ss, off);
    }
    int wid = tid >> 5, lane = tid & 31;
    if (lane == 0) { shs[wid] = s; shss[wid] = ss; }
    __syncthreads();
    float tsum  = shs[0] + shs[1] + shs[2] + shs[3];
    float tsum2 = shss[0] + shss[1] + shss[2] + shss[3];
    float mu  = tsum * (1.f / DM);
    float var = tsum2 * (1.f / DM) - mu * mu;
    float rs  = rsqrtf(var + LN_EPS);

    float4 gv = ((const float4*)gam)[tid];
    float4 bv = ((const float4*)bet)[tid];
    float4 o;
    o.x = (v.x - mu) * rs * gv.x + bv.x;
    o.y = (v.y - mu) * rs * gv.y + bv.y;
    o.z = (v.z - mu) * rs * gv.z + bv.z;
    o.w = (v.w - mu) * rs * gv.w + bv.w;
    ((float4*)(out + (size_t)row * DM))[tid] = o;
}

// ---------------- launch ----------------
static void* symaddr(const void* s) {
    void* p = nullptr;
    cudaGetSymbolAddress(&p, s);
    return p;
}

extern "C" void kernel_launch(void* const* d_in, const int* in_sizes, int n_in,
                              void* d_out, int out_size)
{
    const float* x    = (const float*)d_in[0];
    const float* spos = (const float*)d_in[1];
    const void*  smask = (const void*)d_in[2];
    const float* Wf1 = (const float*)d_in[3];
    const float* bf1 = (const float*)d_in[4];
    const float* Wf2 = (const float*)d_in[5];
    const float* bf2 = (const float*)d_in[6];
    const float* lng = (const float*)d_in[7];
    const float* lnb = (const float*)d_in[8];
    const float* Wd1 = (const float*)d_in[9];
    const float* bd1 = (const float*)d_in[10];
    const float* Wd2 = (const float*)d_in[11];
    const float* bd2 = (const float*)d_in[12];
    float* out = (float*)d_out;

    __nv_bfloat16* xh = (__nv_bfloat16*)symaddr(g_xh);
    __nv_bfloat16* xl = (__nv_bfloat16*)symaddr(g_xl);
    __nv_bfloat16* bh = (__nv_bfloat16*)symaddr(g_bh);
    __nv_bfloat16* bl = (__nv_bfloat16*)symaddr(g_bl);
    __half* hh = (__half*)symaddr(g_hh);
    __half* wh = (__half*)symaddr(g_wh);
    float* zbias = (float*)symaddr(g_zbias);
    float* H     = (float*)symaddr(g_H);
    float* desc  = (float*)symaddr(g_desc);
    float* hd    = (float*)symaddr(g_hd);
    float* tok   = (float*)symaddr(g_tok);

    static int inited = 0;
    static cudaStream_t s1, s2;
    static cudaEvent_t evInit, evC, evD;
    if (!inited) {
        cudaFuncSetAttribute(mma3_kernel,
                             cudaFuncAttributeMaxDynamicSharedMemorySize,
                             MM_SMEM);
        cudaFuncSetAttribute(mma1h_kernel,
                             cudaFuncAttributeMaxDynamicSharedMemorySize,
                             MM2_SMEM);
        cudaStreamCreateWithFlags(&s1, cudaStreamNonBlocking);
        cudaStreamCreateWithFlags(&s2, cudaStreamNonBlocking);
        cudaEventCreateWithFlags(&evInit, cudaEventDisableTiming);
        cudaEventCreateWithFlags(&evC,    cudaEventDisableTiming);
        cudaEventCreateWithFlags(&evD,    cudaEventDisableTiming);
        inited = 1;
    }

    cudaStream_t s0 = 0;   // capture (legacy) stream

    // fork side stream s1 for init work independent of x
    cudaEventRecord(evInit, s0);            // fork point
    cudaStreamWaitEvent(s1, evInit, 0);
    mask_convert_kernel<<<1, 256, 0, s1>>>(smask);
    init_basis_kernel<<<(HCOLS*KPAD + 255)/256, 256, 0, s1>>>();
    w2split_kernel<<<(DM*DM)/256, 256, 0, s1>>>(Wf2);
    cudaEventRecord(evInit, s1);

    // main chain: x split + energy (concurrent with s1)
    xsplit_energy_kernel<<<NROWS_A/8, 256, 0, s0>>>(x);
    cudaStreamWaitEvent(s0, evInit, 0);     // join: basis/mask/w2 ready
    // DFT on tensor cores (bf16 3-pass) -> g_H
    mma3_kernel<<<dim3(1, NROWS_A/128), 256, MM_SMEM, s0>>>(
        xh, xl, bh, bl, H, zbias, KPAD, KPAD, HCOLS, KPAD/32);
    // spectral features + channel reductions
    stageB_kernel<<<NTOK/8, 256, 0, s0>>>(spos);
    stageC_kernel<<<NBW, 64, 0, s0>>>(spos);

    // fork desc branch on s2 (depends only on stageC)
    cudaEventRecord(evC, s0);
    cudaStreamWaitEvent(s2, evC, 0);
    sgemm_bias_act<<<dim3(DM/128, (NBW + 127)/128), 256, 0, s2>>>(
        desc, Wd1, bd1, hd, NBW, DM, 11, 1);
    sgemm_bias_act<<<dim3(DM/128, (NBW + 127)/128), 256, 0, s2>>>(
        hd, Wd2, bd2, out + TOK_ELEMS, NBW, DM, DM, 0);
    cudaEventRecord(evD, s2);

    // token branch on main stream
    gemm1_fused_kernel<<<NTOK/256, 256, 0, s0>>>(Wf1, bf1);
    mma1h_kernel<<<dim3(DM/128, NTOK/128), 256, MM2_SMEM, s0>>>(
        hh, wh, tok, bf2, DM, DM, DM, DM/32);
    ln_kernel<<<NTOK, 128, 0, s0>>>(lng, lnb, out);

    // join desc branch before returning
    cudaStreamWaitEvent(s0, evD, 0);

    (void)in_sizes; (void)n_in; (void)out_size;
}